// round 2
// baseline (speedup 1.0000x reference)
#include <cuda_runtime.h>
#include <math.h>

#define BATCH_  32
#define DIM_    128
#define TLEN_   4096
#define HOP_    256
#define NFR_    17
#define NB_     257
#define SLEN_   4369
#define NPATCH_ 196
#define NFREQ_  99
#define OLA_    4608

static __device__ float  g_ecg_bdt[BATCH_*DIM_*TLEN_];
static __device__ float  g_xsum_bdt[BATCH_*DIM_*TLEN_];
static __device__ float  g_xtext  [BATCH_*DIM_*TLEN_];
static __device__ float2 g_Y      [BATCH_*DIM_*NFR_*NB_];
static __device__ float2 g_fbeff  [DIM_*SLEN_];
static __device__ float2 g_Zimg   [BATCH_*NFREQ_*DIM_];
static __device__ float  g_gate   [BATCH_*DIM_];
static __device__ float  g_ximg   [BATCH_*NPATCH_*DIM_];
static __device__ float  g_normv  [OLA_];

__device__ __forceinline__ float2 cmulf(float2 a, float2 b){
    return make_float2(fmaf(a.x,b.x,-a.y*b.y), fmaf(a.x,b.y,a.y*b.x));
}

template<int SIGN>
__device__ __forceinline__ float2* fft512(float2* bufA, float2* bufB,
                                          const float2* tw, int t){
    float2* src = bufA; float2* dst = bufB;
    #pragma unroll
    for (int i = 0; i < 9; i++){
        int s = 1 << i;
        float2 a = src[t], b = src[t+256];
        float2 w = tw[t & ~(s-1)];
        if (SIGN > 0) w.y = -w.y;
        int pb = ((t>>i) << (i+1)) + (t & (s-1));
        dst[pb] = make_float2(a.x+b.x, a.y+b.y);
        dst[pb+s] = cmulf(make_float2(a.x-b.x, a.y-b.y), w);
        __syncthreads();
        float2* tmp = src; src = dst; dst = tmp;
    }
    return src;
}

__global__ void k_transpose(const float* __restrict__ in, float* __restrict__ out,
                            int R, int C){
    __shared__ float tile[32][33];
    size_t base = (size_t)blockIdx.z * R * C;
    int c0 = blockIdx.x*32, r0 = blockIdx.y*32;
    int tx = threadIdx.x, ty = threadIdx.y;
    #pragma unroll
    for (int k = 0; k < 32; k += 8)
        tile[ty+k][tx] = in[base + (size_t)(r0+ty+k)*C + c0+tx];
    __syncthreads();
    #pragma unroll
    for (int k = 0; k < 32; k += 8)
        out[base + (size_t)(c0+ty+k)*R + r0+tx] = tile[tx][ty+k];
}

__global__ void k_fbeff(const float2* __restrict__ tfb, float2* __restrict__ fbeff,
                        float c0, float c1){
    int s = blockIdx.x, d = threadIdx.x;
    float2 a = tfb[(size_t)s*DIM_ + d];
    float2 b = tfb[((size_t)SLEN_+s)*DIM_ + d];
    fbeff[(size_t)d*SLEN_ + s] = make_float2(c0*a.x+c1*b.x, c0*a.y+c1*b.y);
}

__global__ void k_norm(float* __restrict__ normv){
    int j = blockIdx.x*blockDim.x + threadIdx.x;
    if (j >= OLA_) return;
    float acc = 0.f;
    for (int fr = 0; fr < NFR_; fr++){
        int n = j - fr*HOP_;
        if (n >= 0 && n < 512){
            float w = 0.5f - 0.5f*cosf(6.283185307179586f*(float)n/512.f);
            acc += w*w;
        }
    }
    normv[j] = (acc > 1e-10f) ? acc : 1.f;
}

__global__ void __launch_bounds__(256)
k_stft(const float* __restrict__ ecg_bdt, const float2* __restrict__ fbeff,
       float2* __restrict__ Y){
    __shared__ float2 bufA[512], bufB[512], tw[256];
    __shared__ float win[512];
    int bd = blockIdx.x, d = bd & (DIM_-1), t = threadIdx.x;
    {
        float sn, cs;
        sincosf(-6.283185307179586f*(float)t/512.f, &sn, &cs);
        tw[t] = make_float2(cs, sn);
        for (int n = t; n < 512; n += 256)
            win[n] = 0.5f - 0.5f*cosf(6.283185307179586f*(float)n/512.f);
    }
    const float*  x  = ecg_bdt + (size_t)bd*TLEN_;
    const float2* fe = fbeff + (size_t)d*SLEN_;
    float2* Yb = Y + (size_t)bd*NFR_*NB_;
    const float sc = 1.f/(256.f*256.f*4369.f);
    for (int fr = 0; fr < NFR_; fr++){
        __syncthreads();
        for (int n = t; n < 512; n += 256){
            int tau = fr*HOP_ + n - HOP_;
            float v = (tau >= 0 && tau < TLEN_) ? x[tau] : 0.f;
            bufA[n] = make_float2(v*win[n], 0.f);
        }
        __syncthreads();
        float2* res = fft512<-1>(bufA, bufB, tw, t);
        for (int k = t; k < NB_; k += 256){
            float2 z = res[k];
            float2 z2 = make_float2((z.x*z.x - z.y*z.y)*sc, 2.f*z.x*z.y*sc);
            Yb[fr*NB_ + k] = cmulf(z2, fe[k*NFR_ + fr]);
        }
    }
}

__global__ void __launch_bounds__(256)
k_istft(const float2* __restrict__ Y, const float* __restrict__ normv,
        const float* __restrict__ gate, const float* __restrict__ ecg_bdt,
        float* __restrict__ xsum_bdt){
    __shared__ float2 bufA[512], bufB[512], tw[256];
    __shared__ float win[512], ola[OLA_];
    int bd = blockIdx.x, t = threadIdx.x;
    {
        float sn, cs;
        sincosf(-6.283185307179586f*(float)t/512.f, &sn, &cs);
        tw[t] = make_float2(cs, sn);
    }
    for (int n = t; n < 512; n += 256)
        win[n] = 0.5f - 0.5f*cosf(6.283185307179586f*(float)n/512.f);
    for (int j = t; j < OLA_; j += 256) ola[j] = 0.f;
    const float2* Yb = Y + (size_t)bd*NFR_*NB_;
    for (int fr = 0; fr < NFR_; fr++){
        __syncthreads();
        for (int k = t; k < NB_; k += 256){
            float2 z = Yb[fr*NB_ + k];
            if (k == 0)        bufA[0]   = make_float2(z.x, 0.f);
            else if (k == 256) bufA[256] = make_float2(z.x, 0.f);
            else { bufA[k] = z; bufA[512-k] = make_float2(z.x, -z.y); }
        }
        __syncthreads();
        float2* res = fft512<1>(bufA, bufB, tw, t);
        for (int n = t; n < 512; n += 256)
            ola[fr*HOP_ + n] += res[n].x * 0.5f * win[n];
    }
    __syncthreads();
    float gv = gate[bd];
    const float* xe = ecg_bdt + (size_t)bd*TLEN_;
    float* xo = xsum_bdt + (size_t)bd*TLEN_;
    for (int tau = t; tau < TLEN_; tau += 256){
        int j = tau + HOP_;
        xo[tau] = (ola[j]/normv[j])*gv + xe[tau];
    }
}

__global__ void k_imgfft(const float* __restrict__ image, const float2* __restrict__ ifb,
                         float2* __restrict__ Zimg, float c0, float c1){
    int f = blockIdx.x, b = blockIdx.y, d = threadIdx.x;
    __shared__ float cs[NPATCH_], sn[NPATCH_];
    for (int n = d; n < NPATCH_; n += DIM_){
        int m = (f*n) % NPATCH_;
        float s, c;
        sincosf(-6.283185307179586f*(float)m/(float)NPATCH_, &s, &c);
        cs[n] = c; sn[n] = s;
    }
    __syncthreads();
    const float* xb = image + (size_t)b*NPATCH_*DIM_;
    float ar = 0.f, ai = 0.f;
    for (int n = 0; n < NPATCH_; n++){
        float v = xb[n*DIM_ + d];
        ar = fmaf(v, cs[n], ar);
        ai = fmaf(v, sn[n], ai);
    }
    ar *= (1.f/14.f); ai *= (1.f/14.f);
    float2 fa = ifb[((size_t)0*NFREQ_+f)*DIM_ + d];
    float2 fb = ifb[((size_t)1*NFREQ_+f)*DIM_ + d];
    float2 fe = make_float2(c0*fa.x+c1*fb.x, c0*fa.y+c1*fb.y);
    float2 z2 = make_float2((ar*ar-ai*ai)*(1.f/99.f), 2.f*ar*ai*(1.f/99.f));
    Zimg[((size_t)b*NFREQ_+f)*DIM_ + d] = cmulf(z2, fe);
}

__global__ void k_gate(const float2* __restrict__ Zimg, const float2* __restrict__ sel,
                       const float* __restrict__ w, const float* __restrict__ bias,
                       float* __restrict__ gate){
    int b = blockIdx.x, d = threadIdx.x;
    __shared__ float g[DIM_];
    float acc = 0.f;
    for (int f = 0; f < NFREQ_; f++){
        float2 z = Zimg[((size_t)b*NFREQ_+f)*DIM_ + d];
        float2 s = sel[(size_t)f*DIM_ + d];
        acc += z.x*s.x - z.y*s.y;
    }
    g[d] = acc*(1.f/99.f);
    __syncthreads();
    float o = bias[d];
    for (int k = 0; k < DIM_; k++) o = fmaf(g[k], w[d*DIM_+k], o);
    gate[b*DIM_+d] = o;
}

__global__ void k_imgirfft(const float2* __restrict__ Zimg, const float* __restrict__ image,
                           float* __restrict__ ximg){
    int n = blockIdx.x, b = blockIdx.y, d = threadIdx.x;
    __shared__ float cs[NFREQ_], sn[NFREQ_];
    for (int f = d; f < NFREQ_; f += DIM_){
        int m = (f*n) % NPATCH_;
        float s, c;
        sincosf(6.283185307179586f*(float)m/(float)NPATCH_, &s, &c);
        cs[f] = c; sn[f] = s;
    }
    __syncthreads();
    const float2* Zb = Zimg + (size_t)b*NFREQ_*DIM_;
    float acc = 0.f;
    #pragma unroll 4
    for (int f = 0; f < NFREQ_; f++){
        float wgt = (f == 0 || f == NFREQ_-1) ? 1.f : 2.f;
        float2 z = Zb[f*DIM_ + d];
        acc += wgt*(z.x*cs[f] - z.y*sn[f]);
    }
    size_t idx = ((size_t)b*NPATCH_ + n)*DIM_ + d;
    ximg[idx] = acc*(1.f/14.f) + image[idx];
}

#define AN_XS 132
#define AN_SMEM ((2*16384 + 2*64*AN_XS)*sizeof(float))
__global__ void __launch_bounds__(256)
k_addnorm(const float* __restrict__ xin, float* __restrict__ out,
          const float* __restrict__ g1, const float* __restrict__ b1,
          const float* __restrict__ w1, const float* __restrict__ bb1,
          const float* __restrict__ w2, const float* __restrict__ bb2,
          const float* __restrict__ g2, const float* __restrict__ b2){
    extern __shared__ float sm[];
    float* sW1 = sm;
    float* sW2 = sm + 16384;
    float* sX  = sm + 32768;
    float* sH  = sX + 64*AN_XS;
    const int tid = threadIdx.x;
    for (int i = tid; i < 16384; i += 256){ sW1[i] = w1[i]; sW2[i] = w2[i]; }
    size_t row0 = (size_t)blockIdx.x*64;
    const float* x0 = xin + row0*DIM_;
    for (int i = tid; i < 64*DIM_; i += 256)
        sX[(i>>7)*AN_XS + (i&127)] = x0[i];
    __syncthreads();

    const int warp = tid>>5, lane = tid&31;
    float ga[4], ba[4];
    #pragma unroll
    for (int j = 0; j < 4; j++){ ga[j] = g1[lane+32*j]; ba[j] = b1[lane+32*j]; }
    for (int rr = 0; rr < 8; rr++){
        int r = warp*8 + rr;
        float v[4];
        #pragma unroll
        for (int j = 0; j < 4; j++) v[j] = sX[r*AN_XS + lane+32*j];
        float s = v[0]+v[1]+v[2]+v[3];
        #pragma unroll
        for (int o = 16; o; o >>= 1) s += __shfl_xor_sync(0xffffffffu, s, o);
        float m = s*(1.f/128.f), q = 0.f;
        #pragma unroll
        for (int j = 0; j < 4; j++){ v[j] -= m; q += v[j]*v[j]; }
        #pragma unroll
        for (int o = 16; o; o >>= 1) q += __shfl_xor_sync(0xffffffffu, q, o);
        float inv = rsqrtf(q*(1.f/128.f) + 1e-5f);
        #pragma unroll
        for (int j = 0; j < 4; j++)
            sX[r*AN_XS + lane+32*j] = v[j]*inv*ga[j] + ba[j];
    }
    __syncthreads();

    const int ty = tid>>4, tx = tid&15;
    const int rB = ty*4, cB = tx*8;
    float acc[4][8];
    #pragma unroll
    for (int i = 0; i < 4; i++)
        #pragma unroll
        for (int j = 0; j < 8; j++) acc[i][j] = 0.f;
    #pragma unroll 4
    for (int k = 0; k < 128; k++){
        float a0 = sX[(rB+0)*AN_XS+k], a1 = sX[(rB+1)*AN_XS+k];
        float a2 = sX[(rB+2)*AN_XS+k], a3 = sX[(rB+3)*AN_XS+k];
        float4 bl = *(const float4*)&sW1[k*128+cB];
        float4 bh = *(const float4*)&sW1[k*128+cB+4];
        float bv[8] = {bl.x,bl.y,bl.z,bl.w,bh.x,bh.y,bh.z,bh.w};
        #pragma unroll
        for (int j = 0; j < 8; j++){
            acc[0][j] = fmaf(a0, bv[j], acc[0][j]);
            acc[1][j] = fmaf(a1, bv[j], acc[1][j]);
            acc[2][j] = fmaf(a2, bv[j], acc[2][j]);
            acc[3][j] = fmaf(a3, bv[j], acc[3][j]);
        }
    }
    #pragma unroll
    for (int i = 0; i < 4; i++)
        #pragma unroll
        for (int j = 0; j < 8; j++){
            float h = acc[i][j] + bb1[cB+j];
            h = 0.5f*h*(1.f + erff(h*0.70710678118654752f));
            sH[(rB+i)*AN_XS + cB+j] = h;
        }
    __syncthreads();

    #pragma unroll
    for (int i = 0; i < 4; i++)
        #pragma unroll
        for (int j = 0; j < 8; j++) acc[i][j] = 0.f;
    #pragma unroll 4
    for (int k = 0; k < 128; k++){
        float a0 = sH[(rB+0)*AN_XS+k], a1 = sH[(rB+1)*AN_XS+k];
        float a2 = sH[(rB+2)*AN_XS+k], a3 = sH[(rB+3)*AN_XS+k];
        float4 bl = *(const float4*)&sW2[k*128+cB];
        float4 bh = *(const float4*)&sW2[k*128+cB+4];
        float bv[8] = {bl.x,bl.y,bl.z,bl.w,bh.x,bh.y,bh.z,bh.w};
        #pragma unroll
        for (int j = 0; j < 8; j++){
            acc[0][j] = fmaf(a0, bv[j], acc[0][j]);
            acc[1][j] = fmaf(a1, bv[j], acc[1][j]);
            acc[2][j] = fmaf(a2, bv[j], acc[2][j]);
            acc[3][j] = fmaf(a3, bv[j], acc[3][j]);
        }
    }
    __syncthreads();
    #pragma unroll
    for (int i = 0; i < 4; i++)
        #pragma unroll
        for (int j = 0; j < 8; j++)
            sH[(rB+i)*AN_XS + cB+j] = acc[i][j] + bb2[cB+j] + sX[(rB+i)*AN_XS + cB+j];
    __syncthreads();

    #pragma unroll
    for (int j = 0; j < 4; j++){ ga[j] = g2[lane+32*j]; ba[j] = b2[lane+32*j]; }
    for (int rr = 0; rr < 8; rr++){
        int r = warp*8 + rr;
        float v[4];
        #pragma unroll
        for (int j = 0; j < 4; j++) v[j] = sH[r*AN_XS + lane+32*j];
        float s = v[0]+v[1]+v[2]+v[3];
        #pragma unroll
        for (int o = 16; o; o >>= 1) s += __shfl_xor_sync(0xffffffffu, s, o);
        float m = s*(1.f/128.f), q = 0.f;
        #pragma unroll
        for (int j = 0; j < 4; j++){ v[j] -= m; q += v[j]*v[j]; }
        #pragma unroll
        for (int o = 16; o; o >>= 1) q += __shfl_xor_sync(0xffffffffu, q, o);
        float inv = rsqrtf(q*(1.f/128.f) + 1e-5f);
        #pragma unroll
        for (int j = 0; j < 4; j++)
            out[(row0+r)*DIM_ + lane+32*j] = v[j]*inv*ga[j] + ba[j];
    }
}

extern "C" void kernel_launch(void* const* d_in, const int* in_sizes, int n_in,
                              void* d_out, int out_size){
    (void)in_sizes; (void)n_in; (void)out_size;
    const float* ecg     = (const float*)d_in[0];
    const float* image   = (const float*)d_in[1];
    const float* tfb     = (const float*)d_in[2];
    const float* ifb     = (const float*)d_in[3];
    const float* i2t_sel = (const float*)d_in[4];
    const float* i2t_w   = (const float*)d_in[5];
    const float* i2t_b   = (const float*)d_in[6];
    const float* t_ln1_g = (const float*)d_in[7];
    const float* t_ln1_b = (const float*)d_in[8];
    const float* t_w1    = (const float*)d_in[9];
    const float* t_b1    = (const float*)d_in[10];
    const float* t_w2    = (const float*)d_in[11];
    const float* t_b2    = (const float*)d_in[12];
    const float* t_ln2_g = (const float*)d_in[13];
    const float* t_ln2_b = (const float*)d_in[14];
    const float* i_ln1_g = (const float*)d_in[15];
    const float* i_ln1_b = (const float*)d_in[16];
    const float* i_w1    = (const float*)d_in[17];
    const float* i_b1    = (const float*)d_in[18];
    const float* i_w2    = (const float*)d_in[19];
    const float* i_b2    = (const float*)d_in[20];
    const float* i_ln2_g = (const float*)d_in[21];
    const float* i_ln2_b = (const float*)d_in[22];

    void* p;
    cudaGetSymbolAddress(&p, g_ecg_bdt);  float*  ecg_bdt = (float*)p;
    cudaGetSymbolAddress(&p, g_xsum_bdt); float*  xsum    = (float*)p;
    cudaGetSymbolAddress(&p, g_xtext);    float*  xtext   = (float*)p;
    cudaGetSymbolAddress(&p, g_Y);        float2* Yp      = (float2*)p;
    cudaGetSymbolAddress(&p, g_fbeff);    float2* fbeff   = (float2*)p;
    cudaGetSymbolAddress(&p, g_Zimg);     float2* Zimg    = (float2*)p;
    cudaGetSymbolAddress(&p, g_gate);     float*  gate    = (float*)p;
    cudaGetSymbolAddress(&p, g_ximg);     float*  ximg    = (float*)p;
    cudaGetSymbolAddress(&p, g_normv);    float*  normv   = (float*)p;

    float c0 = cosf(1.f*3.1415926f);
    float c1 = cosf(3.f*3.1415926f);

    static int attr_done = 0;
    cudaFuncSetAttribute(k_addnorm, cudaFuncAttributeMaxDynamicSharedMemorySize,
                         (int)AN_SMEM);
    (void)attr_done;

    float* text_out = (float*)d_out;
    float* img_out  = (float*)d_out + (size_t)BATCH_*TLEN_*DIM_;

    k_transpose<<<dim3(DIM_/32, TLEN_/32, BATCH_), dim3(32,8)>>>(ecg, ecg_bdt, TLEN_, DIM_);
    k_fbeff<<<SLEN_, DIM_>>>((const float2*)tfb, fbeff, c0, c1);
    k_norm<<<(OLA_+255)/256, 256>>>(normv);
    k_stft<<<BATCH_*DIM_, 256>>>(ecg_bdt, fbeff, Yp);
    k_imgfft<<<dim3(NFREQ_, BATCH_), DIM_>>>(image, (const float2*)ifb, Zimg, c0, c1);
    k_gate<<<BATCH_, DIM_>>>(Zimg, (const float2*)i2t_sel, i2t_w, i2t_b, gate);
    k_istft<<<BATCH_*DIM_, 256>>>(Yp, normv, gate, ecg_bdt, xsum);
    k_transpose<<<dim3(TLEN_/32, DIM_/32, BATCH_), dim3(32,8)>>>(xsum, xtext, DIM_, TLEN_);
    k_addnorm<<<(BATCH_*TLEN_)/64, 256, AN_SMEM>>>(xtext, text_out,
        t_ln1_g, t_ln1_b, t_w1, t_b1, t_w2, t_b2, t_ln2_g, t_ln2_b);
    k_imgirfft<<<dim3(NPATCH_, BATCH_), DIM_>>>(Zimg, image, ximg);
    k_addnorm<<<(BATCH_*NPATCH_)/64, 256, AN_SMEM>>>(ximg, img_out,
        i_ln1_g, i_ln1_b, i_w1, i_b1, i_w2, i_b2, i_ln2_g, i_ln2_b);
}

// round 3
// speedup vs baseline: 1.1918x; 1.1918x over previous
#include <cuda_runtime.h>
#include <math.h>

#define BATCH_  32
#define DIM_    128
#define TLEN_   4096
#define HOP_    256
#define NFR_    17
#define NB_     257
#define SLEN_   4369
#define NPATCH_ 196
#define NFREQ_  99
#define OLA_    4608

static __device__ float  g_ecg_bdt[BATCH_*DIM_*TLEN_];
static __device__ float  g_xsum_bdt[BATCH_*DIM_*TLEN_];
static __device__ float2 g_fbeff  [DIM_*SLEN_];
static __device__ float2 g_Zimg   [BATCH_*NFREQ_*DIM_];
static __device__ float  g_gate   [BATCH_*DIM_];
static __device__ float  g_ximg   [BATCH_*NPATCH_*DIM_];
static __device__ float  g_normv  [OLA_];

// ---------------- radix-8 register FFT pieces ---------------------------------
// FFT8 (DIF). After this, natural-order Y[j] = x[brev[j]], brev={0,4,2,6,1,5,3,7}.
template<int SIGN>
__device__ __forceinline__ void fft8(float* r, float* i){
    const float c = 0.70710678118654752f;
    float ur[4], ui[4], vr[4], vi[4];
    #pragma unroll
    for (int q = 0; q < 4; q++){
        ur[q] = r[q] + r[q+4]; ui[q] = i[q] + i[q+4];
        vr[q] = r[q] - r[q+4]; vi[q] = i[q] - i[q+4];
    }
    { float x = vr[1], y = vi[1];
      if (SIGN < 0){ vr[1] = c*(x+y); vi[1] = c*(y-x); }
      else         { vr[1] = c*(x-y); vi[1] = c*(x+y); } }
    { float x = vr[2], y = vi[2];
      if (SIGN < 0){ vr[2] = y;  vi[2] = -x; }
      else         { vr[2] = -y; vi[2] = x;  } }
    { float x = vr[3], y = vi[3];
      if (SIGN < 0){ vr[3] = c*(y-x);  vi[3] = -c*(x+y); }
      else         { vr[3] = -c*(x+y); vi[3] = c*(x-y);  } }
    float p0r = ur[0]+ur[2], p0i = ui[0]+ui[2];
    float p2r = ur[0]-ur[2], p2i = ui[0]-ui[2];
    float p1r = ur[1]+ur[3], p1i = ui[1]+ui[3];
    float t3r = ur[1]-ur[3], t3i = ui[1]-ui[3];
    float p3r, p3i;
    if (SIGN < 0){ p3r = t3i; p3i = -t3r; } else { p3r = -t3i; p3i = t3r; }
    float q0r = vr[0]+vr[2], q0i = vi[0]+vi[2];
    float q2r = vr[0]-vr[2], q2i = vi[0]-vi[2];
    float q1r = vr[1]+vr[3], q1i = vi[1]+vi[3];
    float s3r = vr[1]-vr[3], s3i = vi[1]-vi[3];
    float q3r, q3i;
    if (SIGN < 0){ q3r = s3i; q3i = -s3r; } else { q3r = -s3i; q3i = s3r; }
    r[0] = p0r+p1r; i[0] = p0i+p1i;
    r[1] = p0r-p1r; i[1] = p0i-p1i;
    r[2] = p2r+p3r; i[2] = p2i+p3i;
    r[3] = p2r-p3r; i[3] = p2i-p3i;
    r[4] = q0r+q1r; i[4] = q0i+q1i;
    r[5] = q0r-q1r; i[5] = q0i-q1i;
    r[6] = q2r+q3r; i[6] = q2i+q3i;
    r[7] = q2r-q3r; i[7] = q2i-q3i;
}

#define PHYS(idx) ((idx) + ((idx) >> 3))

// One Stockham radix-8 stage, N=512, 64 threads, stage span S in {1,8,64}.
// twR[m]=cos(2pi m/512), twI[m]=-sin(2pi m/512) (forward sign baked in).
template<int SIGN, int S>
__device__ __forceinline__ void r8stage(const float* __restrict__ sR,
                                        const float* __restrict__ sI,
                                        float* __restrict__ dR,
                                        float* __restrict__ dI,
                                        const float* __restrict__ twR,
                                        const float* __restrict__ twI, int t){
    float xr[8], xi[8];
    #pragma unroll
    for (int q = 0; q < 8; q++){
        int idx = t + 64*q;
        xr[q] = sR[PHYS(idx)]; xi[q] = sI[PHYS(idx)];
    }
    fft8<SIGN>(xr, xi);
    const int brev[8] = {0,4,2,6,1,5,3,7};
    int hi = t / S, lo = t % S;
    int base = hi*8*S + lo;
    int tb = hi*S;
    #pragma unroll
    for (int j = 0; j < 8; j++){
        float yr = xr[brev[j]], yi = xi[brev[j]];
        int m = (tb*j) & 511;
        float wr = twR[m];
        float wi = (SIGN < 0) ? twI[m] : -twI[m];
        float zr = yr*wr - yi*wi;
        float zi = yr*wi + yi*wr;
        int idx = base + j*S;
        dR[PHYS(idx)] = zr; dI[PHYS(idx)] = zi;
    }
}

// ---------------- small kernels ------------------------------------------------
__global__ void k_transpose(const float* __restrict__ in, float* __restrict__ out,
                            int R, int C){
    __shared__ float tile[32][33];
    size_t base = (size_t)blockIdx.z * R * C;
    int c0 = blockIdx.x*32, r0 = blockIdx.y*32;
    int tx = threadIdx.x, ty = threadIdx.y;
    #pragma unroll
    for (int k = 0; k < 32; k += 8)
        tile[ty+k][tx] = in[base + (size_t)(r0+ty+k)*C + c0+tx];
    __syncthreads();
    #pragma unroll
    for (int k = 0; k < 32; k += 8)
        out[base + (size_t)(c0+ty+k)*R + r0+tx] = tile[tx][ty+k];
}

// fbeff layout: [d][fr*257 + k];  reference s = k*17 + fr
__global__ void k_fbeff(const float2* __restrict__ tfb, float2* __restrict__ fbeff,
                        float c0, float c1){
    int s = blockIdx.x, d = threadIdx.x;
    int k = s / NFR_, fr = s % NFR_;
    float2 a = tfb[(size_t)s*DIM_ + d];
    float2 b = tfb[((size_t)SLEN_+s)*DIM_ + d];
    fbeff[(size_t)d*SLEN_ + fr*NB_ + k] =
        make_float2(c0*a.x + c1*b.x, c0*a.y + c1*b.y);
}

__global__ void k_norm(float* __restrict__ normv){
    int j = blockIdx.x*blockDim.x + threadIdx.x;
    if (j >= OLA_) return;
    float acc = 0.f;
    for (int fr = 0; fr < NFR_; fr++){
        int n = j - fr*HOP_;
        if (n >= 0 && n < 512){
            float w = 0.5f - 0.5f*cosf(6.283185307179586f*(float)n/512.f);
            acc += w*w;
        }
    }
    normv[j] = (acc > 1e-10f) ? acc : 1.f;
}

// ---------------- fused STFT -> filter -> gate -> ISTFT -> residual ------------
// block per (b,d); 256 threads = 4 groups x 64; 4 frames in flight per round
#define FS_SMEM 61440
__global__ void __launch_bounds__(256)
k_fsru(const float* __restrict__ ecg_bdt, const float2* __restrict__ fbeff,
       const float* __restrict__ normv, const float* __restrict__ gate,
       float* __restrict__ xsum){
    extern __shared__ float sm[];
    float* twR  = sm;                 // 512
    float* twI  = sm + 512;           // 512
    float* win  = sm + 1024;          // 512
    float* ola  = sm + 1536;          // 4608
    float* bufs = sm + 1536 + OLA_;   // 4 groups * 4 arrays * 576
    int tid = threadIdx.x, g = tid >> 6, t = tid & 63;
    int bd = blockIdx.x, d = bd & (DIM_-1);
    float* AR = bufs + (g*4+0)*576;
    float* AI = bufs + (g*4+1)*576;
    float* BR = bufs + (g*4+2)*576;
    float* BI = bufs + (g*4+3)*576;
    for (int m = tid; m < 512; m += 256){
        float s, c;
        sincosf(6.283185307179586f*(float)m/512.f, &s, &c);
        twR[m] = c; twI[m] = -s;
        win[m] = 0.5f - 0.5f*c;
    }
    for (int j = tid; j < OLA_; j += 256) ola[j] = 0.f;
    const float*  x  = ecg_bdt + (size_t)bd*TLEN_;
    const float2* fe = fbeff + (size_t)d*SLEN_;
    const float sc = 1.f/(256.f*256.f*4369.f);
    __syncthreads();

    for (int rr = 0; rr < 5; rr++){
        int fr = rr*4 + g;
        bool act = (fr < NFR_);
        if (act){
            #pragma unroll
            for (int q = 0; q < 8; q++){
                int idx = t + 64*q;
                int tau = fr*HOP_ + idx - HOP_;
                float v = (tau >= 0 && tau < TLEN_) ? x[tau] : 0.f;
                AR[PHYS(idx)] = v*win[idx]; AI[PHYS(idx)] = 0.f;
            }
        }
        __syncthreads();
        if (act) r8stage<-1,1 >(AR,AI,BR,BI,twR,twI,t);
        __syncthreads();
        if (act) r8stage<-1,8 >(BR,BI,AR,AI,twR,twI,t);
        __syncthreads();
        if (act) r8stage<-1,64>(AR,AI,BR,BI,twR,twI,t);
        __syncthreads();
        if (act){
            #pragma unroll
            for (int q = 0; q < 8; q++){
                int k = t + 64*q; int p = PHYS(k);
                float zr = BR[p], zi = BI[p];
                float z2r = (zr*zr - zi*zi)*sc, z2i = 2.f*zr*zi*sc;
                int m = (k <= 256) ? k : 512 - k;
                float2 f = fe[fr*NB_ + m];
                float fi = (k <= 256) ? f.y : -f.y;
                float yr = z2r*f.x - z2i*fi;
                float yi = z2r*fi + z2i*f.x;
                if (k == 0 || k == 256) yi = 0.f;
                AR[p] = yr; AI[p] = yi;
            }
        }
        __syncthreads();
        if (act) r8stage<1,1 >(AR,AI,BR,BI,twR,twI,t);
        __syncthreads();
        if (act) r8stage<1,8 >(BR,BI,AR,AI,twR,twI,t);
        __syncthreads();
        if (act) r8stage<1,64>(AR,AI,BR,BI,twR,twI,t);
        // final stage wrote exactly the positions this thread reads below
        if (act){
            #pragma unroll
            for (int q = 0; q < 8; q++){
                int n = t + 64*q;
                atomicAdd(&ola[fr*HOP_ + n], BR[PHYS(n)]*0.5f*win[n]);
            }
        }
        __syncthreads();
    }
    float gv = gate[bd];
    float* xo = xsum + (size_t)bd*TLEN_;
    for (int tau = tid; tau < TLEN_; tau += 256){
        int j = tau + HOP_;
        xo[tau] = (ola[j]/normv[j])*gv + x[tau];
    }
}

// ---------------- image path ---------------------------------------------------
__global__ void k_imgfft(const float* __restrict__ image, const float2* __restrict__ ifb,
                         float2* __restrict__ Zimg, float c0, float c1){
    int f = blockIdx.x, b = blockIdx.y, d = threadIdx.x;
    __shared__ float cs[NPATCH_], sn[NPATCH_];
    for (int n = d; n < NPATCH_; n += DIM_){
        int m = (f*n) % NPATCH_;
        float s, c;
        sincosf(-6.283185307179586f*(float)m/(float)NPATCH_, &s, &c);
        cs[n] = c; sn[n] = s;
    }
    __syncthreads();
    const float* xb = image + (size_t)b*NPATCH_*DIM_;
    float ar = 0.f, ai = 0.f;
    for (int n = 0; n < NPATCH_; n++){
        float v = xb[n*DIM_ + d];
        ar = fmaf(v, cs[n], ar);
        ai = fmaf(v, sn[n], ai);
    }
    ar *= (1.f/14.f); ai *= (1.f/14.f);
    float2 fa = ifb[((size_t)0*NFREQ_+f)*DIM_ + d];
    float2 fb = ifb[((size_t)1*NFREQ_+f)*DIM_ + d];
    float2 feff = make_float2(c0*fa.x+c1*fb.x, c0*fa.y+c1*fb.y);
    float z2r = (ar*ar - ai*ai)*(1.f/99.f), z2i = 2.f*ar*ai*(1.f/99.f);
    Zimg[((size_t)b*NFREQ_+f)*DIM_ + d] =
        make_float2(z2r*feff.x - z2i*feff.y, z2r*feff.y + z2i*feff.x);
}

__global__ void k_gate(const float2* __restrict__ Zimg, const float2* __restrict__ sel,
                       const float* __restrict__ w, const float* __restrict__ bias,
                       float* __restrict__ gate){
    int b = blockIdx.x, d = threadIdx.x;
    __shared__ float g[DIM_];
    float acc = 0.f;
    for (int f = 0; f < NFREQ_; f++){
        float2 z = Zimg[((size_t)b*NFREQ_+f)*DIM_ + d];
        float2 s = sel[(size_t)f*DIM_ + d];
        acc += z.x*s.x - z.y*s.y;
    }
    g[d] = acc*(1.f/99.f);
    __syncthreads();
    float o = bias[d];
    for (int k = 0; k < DIM_; k++) o = fmaf(g[k], w[d*DIM_+k], o);
    gate[b*DIM_+d] = o;
}

__global__ void k_imgirfft(const float2* __restrict__ Zimg, const float* __restrict__ image,
                           float* __restrict__ ximg){
    int n = blockIdx.x, b = blockIdx.y, d = threadIdx.x;
    __shared__ float cs[NFREQ_], sn[NFREQ_];
    for (int f = d; f < NFREQ_; f += DIM_){
        int m = (f*n) % NPATCH_;
        float s, c;
        sincosf(6.283185307179586f*(float)m/(float)NPATCH_, &s, &c);
        cs[f] = c; sn[f] = s;
    }
    __syncthreads();
    const float2* Zb = Zimg + (size_t)b*NFREQ_*DIM_;
    float acc = 0.f;
    #pragma unroll 4
    for (int f = 0; f < NFREQ_; f++){
        float wgt = (f == 0 || f == NFREQ_-1) ? 1.f : 2.f;
        float2 z = Zb[f*DIM_ + d];
        acc += wgt*(z.x*cs[f] - z.y*sn[f]);
    }
    size_t idx = ((size_t)b*NPATCH_ + n)*DIM_ + d;
    ximg[idx] = acc*(1.f/14.f) + image[idx];
}

// ---------------- fused AddNorm ------------------------------------------------
#define AN_XS 132
#define AN_SMEM ((2*16384 + 2*64*AN_XS)*sizeof(float))
template<bool TRANS>
__global__ void __launch_bounds__(256)
k_addnorm(const float* __restrict__ xin, float* __restrict__ out,
          const float* __restrict__ g1, const float* __restrict__ b1,
          const float* __restrict__ w1, const float* __restrict__ bb1,
          const float* __restrict__ w2, const float* __restrict__ bb2,
          const float* __restrict__ g2, const float* __restrict__ b2){
    extern __shared__ float sm[];
    float* sW1 = sm;
    float* sW2 = sm + 16384;
    float* sX  = sm + 32768;
    float* sH  = sX + 64*AN_XS;
    const int tid = threadIdx.x;
    for (int i = tid; i < 16384; i += 256){ sW1[i] = w1[i]; sW2[i] = w2[i]; }
    size_t row0 = (size_t)blockIdx.x*64;
    if (TRANS){
        // xin is (B, D, T): token row = b*T + tok; feature d strided by T
        int b = (int)(row0 >> 12), tok0 = (int)(row0 & 4095);
        const float* xb = xin + ((size_t)b*DIM_)*TLEN_ + tok0;
        for (int i = tid; i < DIM_*64; i += 256){
            int dd = i >> 6, c = i & 63;
            sX[c*AN_XS + dd] = xb[(size_t)dd*TLEN_ + c];
        }
    } else {
        const float* x0 = xin + row0*DIM_;
        for (int i = tid; i < 64*DIM_; i += 256)
            sX[(i>>7)*AN_XS + (i&127)] = x0[i];
    }
    __syncthreads();

    const int warp = tid>>5, lane = tid&31;
    float ga[4], ba[4];
    #pragma unroll
    for (int j = 0; j < 4; j++){ ga[j] = g1[lane+32*j]; ba[j] = b1[lane+32*j]; }
    for (int rr = 0; rr < 8; rr++){
        int r = warp*8 + rr;
        float v[4];
        #pragma unroll
        for (int j = 0; j < 4; j++) v[j] = sX[r*AN_XS + lane+32*j];
        float s = v[0]+v[1]+v[2]+v[3];
        #pragma unroll
        for (int o = 16; o; o >>= 1) s += __shfl_xor_sync(0xffffffffu, s, o);
        float m = s*(1.f/128.f), q = 0.f;
        #pragma unroll
        for (int j = 0; j < 4; j++){ v[j] -= m; q += v[j]*v[j]; }
        #pragma unroll
        for (int o = 16; o; o >>= 1) q += __shfl_xor_sync(0xffffffffu, q, o);
        float inv = rsqrtf(q*(1.f/128.f) + 1e-5f);
        #pragma unroll
        for (int j = 0; j < 4; j++)
            sX[r*AN_XS + lane+32*j] = v[j]*inv*ga[j] + ba[j];
    }
    __syncthreads();

    const int ty = tid>>4, tx = tid&15;
    const int rB = ty*4, cB = tx*8;
    float acc[4][8];
    #pragma unroll
    for (int i = 0; i < 4; i++)
        #pragma unroll
        for (int j = 0; j < 8; j++) acc[i][j] = 0.f;
    #pragma unroll 4
    for (int k = 0; k < 128; k++){
        float a0 = sX[(rB+0)*AN_XS+k], a1 = sX[(rB+1)*AN_XS+k];
        float a2 = sX[(rB+2)*AN_XS+k], a3 = sX[(rB+3)*AN_XS+k];
        float4 bl = *(const float4*)&sW1[k*128+cB];
        float4 bh = *(const float4*)&sW1[k*128+cB+4];
        float bv[8] = {bl.x,bl.y,bl.z,bl.w,bh.x,bh.y,bh.z,bh.w};
        #pragma unroll
        for (int j = 0; j < 8; j++){
            acc[0][j] = fmaf(a0, bv[j], acc[0][j]);
            acc[1][j] = fmaf(a1, bv[j], acc[1][j]);
            acc[2][j] = fmaf(a2, bv[j], acc[2][j]);
            acc[3][j] = fmaf(a3, bv[j], acc[3][j]);
        }
    }
    #pragma unroll
    for (int i = 0; i < 4; i++)
        #pragma unroll
        for (int j = 0; j < 8; j++){
            float h = acc[i][j] + bb1[cB+j];
            h = 0.5f*h*(1.f + erff(h*0.70710678118654752f));
            sH[(rB+i)*AN_XS + cB+j] = h;
        }
    __syncthreads();

    #pragma unroll
    for (int i = 0; i < 4; i++)
        #pragma unroll
        for (int j = 0; j < 8; j++) acc[i][j] = 0.f;
    #pragma unroll 4
    for (int k = 0; k < 128; k++){
        float a0 = sH[(rB+0)*AN_XS+k], a1 = sH[(rB+1)*AN_XS+k];
        float a2 = sH[(rB+2)*AN_XS+k], a3 = sH[(rB+3)*AN_XS+k];
        float4 bl = *(const float4*)&sW2[k*128+cB];
        float4 bh = *(const float4*)&sW2[k*128+cB+4];
        float bv[8] = {bl.x,bl.y,bl.z,bl.w,bh.x,bh.y,bh.z,bh.w};
        #pragma unroll
        for (int j = 0; j < 8; j++){
            acc[0][j] = fmaf(a0, bv[j], acc[0][j]);
            acc[1][j] = fmaf(a1, bv[j], acc[1][j]);
            acc[2][j] = fmaf(a2, bv[j], acc[2][j]);
            acc[3][j] = fmaf(a3, bv[j], acc[3][j]);
        }
    }
    __syncthreads();
    #pragma unroll
    for (int i = 0; i < 4; i++)
        #pragma unroll
        for (int j = 0; j < 8; j++)
            sH[(rB+i)*AN_XS + cB+j] = acc[i][j] + bb2[cB+j] + sX[(rB+i)*AN_XS + cB+j];
    __syncthreads();

    #pragma unroll
    for (int j = 0; j < 4; j++){ ga[j] = g2[lane+32*j]; ba[j] = b2[lane+32*j]; }
    for (int rr = 0; rr < 8; rr++){
        int r = warp*8 + rr;
        float v[4];
        #pragma unroll
        for (int j = 0; j < 4; j++) v[j] = sH[r*AN_XS + lane+32*j];
        float s = v[0]+v[1]+v[2]+v[3];
        #pragma unroll
        for (int o = 16; o; o >>= 1) s += __shfl_xor_sync(0xffffffffu, s, o);
        float m = s*(1.f/128.f), q = 0.f;
        #pragma unroll
        for (int j = 0; j < 4; j++){ v[j] -= m; q += v[j]*v[j]; }
        #pragma unroll
        for (int o = 16; o; o >>= 1) q += __shfl_xor_sync(0xffffffffu, q, o);
        float inv = rsqrtf(q*(1.f/128.f) + 1e-5f);
        #pragma unroll
        for (int j = 0; j < 4; j++)
            out[(row0+r)*DIM_ + lane+32*j] = v[j]*inv*ga[j] + ba[j];
    }
}

extern "C" void kernel_launch(void* const* d_in, const int* in_sizes, int n_in,
                              void* d_out, int out_size){
    (void)in_sizes; (void)n_in; (void)out_size;
    const float* ecg     = (const float*)d_in[0];
    const float* image   = (const float*)d_in[1];
    const float* tfb     = (const float*)d_in[2];
    const float* ifb     = (const float*)d_in[3];
    const float* i2t_sel = (const float*)d_in[4];
    const float* i2t_w   = (const float*)d_in[5];
    const float* i2t_b   = (const float*)d_in[6];
    const float* t_ln1_g = (const float*)d_in[7];
    const float* t_ln1_b = (const float*)d_in[8];
    const float* t_w1    = (const float*)d_in[9];
    const float* t_b1    = (const float*)d_in[10];
    const float* t_w2    = (const float*)d_in[11];
    const float* t_b2    = (const float*)d_in[12];
    const float* t_ln2_g = (const float*)d_in[13];
    const float* t_ln2_b = (const float*)d_in[14];
    const float* i_ln1_g = (const float*)d_in[15];
    const float* i_ln1_b = (const float*)d_in[16];
    const float* i_w1    = (const float*)d_in[17];
    const float* i_b1    = (const float*)d_in[18];
    const float* i_w2    = (const float*)d_in[19];
    const float* i_b2    = (const float*)d_in[20];
    const float* i_ln2_g = (const float*)d_in[21];
    const float* i_ln2_b = (const float*)d_in[22];

    void* p;
    cudaGetSymbolAddress(&p, g_ecg_bdt);  float*  ecg_bdt = (float*)p;
    cudaGetSymbolAddress(&p, g_xsum_bdt); float*  xsum    = (float*)p;
    cudaGetSymbolAddress(&p, g_fbeff);    float2* fbeff   = (float2*)p;
    cudaGetSymbolAddress(&p, g_Zimg);     float2* Zimg    = (float2*)p;
    cudaGetSymbolAddress(&p, g_gate);     float*  gate    = (float*)p;
    cudaGetSymbolAddress(&p, g_ximg);     float*  ximg    = (float*)p;
    cudaGetSymbolAddress(&p, g_normv);    float*  normv   = (float*)p;

    float c0 = cosf(1.f*3.1415926f);
    float c1 = cosf(3.f*3.1415926f);

    cudaFuncSetAttribute(k_fsru, cudaFuncAttributeMaxDynamicSharedMemorySize, FS_SMEM);
    cudaFuncSetAttribute(k_addnorm<true>,  cudaFuncAttributeMaxDynamicSharedMemorySize, (int)AN_SMEM);
    cudaFuncSetAttribute(k_addnorm<false>, cudaFuncAttributeMaxDynamicSharedMemorySize, (int)AN_SMEM);

    float* text_out = (float*)d_out;
    float* img_out  = (float*)d_out + (size_t)BATCH_*TLEN_*DIM_;

    k_transpose<<<dim3(DIM_/32, TLEN_/32, BATCH_), dim3(32,8)>>>(ecg, ecg_bdt, TLEN_, DIM_);
    k_fbeff<<<SLEN_, DIM_>>>((const float2*)tfb, fbeff, c0, c1);
    k_norm<<<(OLA_+255)/256, 256>>>(normv);
    k_imgfft<<<dim3(NFREQ_, BATCH_), DIM_>>>(image, (const float2*)ifb, Zimg, c0, c1);
    k_gate<<<BATCH_, DIM_>>>(Zimg, (const float2*)i2t_sel, i2t_w, i2t_b, gate);
    k_fsru<<<BATCH_*DIM_, 256, FS_SMEM>>>(ecg_bdt, fbeff, normv, gate, xsum);
    k_addnorm<true><<<(BATCH_*TLEN_)/64, 256, AN_SMEM>>>(xsum, text_out,
        t_ln1_g, t_ln1_b, t_w1, t_b1, t_w2, t_b2, t_ln2_g, t_ln2_b);
    k_imgirfft<<<dim3(NPATCH_, BATCH_), DIM_>>>(Zimg, image, ximg);
    k_addnorm<false><<<(BATCH_*NPATCH_)/64, 256, AN_SMEM>>>(ximg, img_out,
        i_ln1_g, i_ln1_b, i_w1, i_b1, i_w2, i_b2, i_ln2_g, i_ln2_b);
}

// round 7
// speedup vs baseline: 1.3785x; 1.1566x over previous
#include <cuda_runtime.h>
#include <math.h>
#include <stdint.h>
#include <mma.h>
using namespace nvcuda;

#define BATCH_  32
#define DIM_    128
#define TLEN_   4096
#define HOP_    256
#define NFR_    17
#define NB_     257
#define SLEN_   4369
#define NPATCH_ 196
#define NFREQ_  99
#define OLA_    4608

static __device__ float  g_ecg_bdt[BATCH_*DIM_*TLEN_];
static __device__ float  g_xsum_bdt[BATCH_*DIM_*TLEN_];
static __device__ float2 g_fbeff  [DIM_*SLEN_];
static __device__ float2 g_Zimg   [BATCH_*NFREQ_*DIM_];
static __device__ float  g_gate   [BATCH_*DIM_];
static __device__ float  g_ximg   [BATCH_*NPATCH_*DIM_];
static __device__ float  g_normv  [OLA_];

// ======================= radix-8 FFT =======================
template<int SIGN>
__device__ __forceinline__ void fft8(float* r, float* i){
    const float c = 0.70710678118654752f;
    float ur[4], ui[4], vr[4], vi[4];
    #pragma unroll
    for (int q = 0; q < 4; q++){
        ur[q] = r[q] + r[q+4]; ui[q] = i[q] + i[q+4];
        vr[q] = r[q] - r[q+4]; vi[q] = i[q] - i[q+4];
    }
    { float x = vr[1], y = vi[1];
      if (SIGN < 0){ vr[1] = c*(x+y); vi[1] = c*(y-x); }
      else         { vr[1] = c*(x-y); vi[1] = c*(x+y); } }
    { float x = vr[2], y = vi[2];
      if (SIGN < 0){ vr[2] = y;  vi[2] = -x; }
      else         { vr[2] = -y; vi[2] = x;  } }
    { float x = vr[3], y = vi[3];
      if (SIGN < 0){ vr[3] = c*(y-x);  vi[3] = -c*(x+y); }
      else         { vr[3] = -c*(x+y); vi[3] = c*(x-y);  } }
    float p0r = ur[0]+ur[2], p0i = ui[0]+ui[2];
    float p2r = ur[0]-ur[2], p2i = ui[0]-ui[2];
    float p1r = ur[1]+ur[3], p1i = ui[1]+ui[3];
    float t3r = ur[1]-ur[3], t3i = ui[1]-ui[3];
    float p3r, p3i;
    if (SIGN < 0){ p3r = t3i; p3i = -t3r; } else { p3r = -t3i; p3i = t3r; }
    float q0r = vr[0]+vr[2], q0i = vi[0]+vi[2];
    float q2r = vr[0]-vr[2], q2i = vi[0]-vi[2];
    float q1r = vr[1]+vr[3], q1i = vi[1]+vi[3];
    float s3r = vr[1]-vr[3], s3i = vi[1]-vi[3];
    float q3r, q3i;
    if (SIGN < 0){ q3r = s3i; q3i = -s3r; } else { q3r = -s3i; q3i = s3r; }
    r[0] = p0r+p1r; i[0] = p0i+p1i;
    r[1] = p0r-p1r; i[1] = p0i-p1i;
    r[2] = p2r+p3r; i[2] = p2i+p3i;
    r[3] = p2r-p3r; i[3] = p2i-p3i;
    r[4] = q0r+q1r; i[4] = q0i+q1i;
    r[5] = q0r-q1r; i[5] = q0i-q1i;
    r[6] = q2r+q3r; i[6] = q2i+q3i;
    r[7] = q2r-q3r; i[7] = q2i-q3i;
}

#define PHYS(idx) ((idx) + ((idx) >> 3))

template<int SIGN, int S>
__device__ __forceinline__ void r8stage(const float* __restrict__ sR,
                                        const float* __restrict__ sI,
                                        float* __restrict__ dR,
                                        float* __restrict__ dI,
                                        const float* __restrict__ twR,
                                        const float* __restrict__ twI, int t){
    float xr[8], xi[8];
    #pragma unroll
    for (int q = 0; q < 8; q++){
        int idx = t + 64*q;
        xr[q] = sR[PHYS(idx)]; xi[q] = sI[PHYS(idx)];
    }
    fft8<SIGN>(xr, xi);
    const int brev[8] = {0,4,2,6,1,5,3,7};
    int hi = t / S, lo = t % S;
    int base = hi*8*S + lo;
    int tb = hi*S;
    #pragma unroll
    for (int j = 0; j < 8; j++){
        float yr = xr[brev[j]], yi = xi[brev[j]];
        int m = (tb*j) & 511;
        float wr = twR[m];
        float wi = (SIGN < 0) ? twI[m] : -twI[m];
        int idx = base + j*S;
        dR[PHYS(idx)] = yr*wr - yi*wi;
        dI[PHYS(idx)] = yr*wi + yi*wr;
    }
}

// ======================= small kernels =========================================
__global__ void k_transpose(const float* __restrict__ in, float* __restrict__ out,
                            int R, int C){
    __shared__ float tile[32][33];
    size_t base = (size_t)blockIdx.z * R * C;
    int c0 = blockIdx.x*32, r0 = blockIdx.y*32;
    int tx = threadIdx.x, ty = threadIdx.y;
    #pragma unroll
    for (int k = 0; k < 32; k += 8)
        tile[ty+k][tx] = in[base + (size_t)(r0+ty+k)*C + c0+tx];
    __syncthreads();
    #pragma unroll
    for (int k = 0; k < 32; k += 8)
        out[base + (size_t)(c0+ty+k)*R + r0+tx] = tile[tx][ty+k];
}

__global__ void k_fbeff(const float2* __restrict__ tfb, float2* __restrict__ fbeff,
                        float c0, float c1){
    int s = blockIdx.x, d = threadIdx.x;
    int k = s / NFR_, fr = s % NFR_;
    float2 a = tfb[(size_t)s*DIM_ + d];
    float2 b = tfb[((size_t)SLEN_+s)*DIM_ + d];
    fbeff[(size_t)d*SLEN_ + fr*NB_ + k] =
        make_float2(c0*a.x + c1*b.x, c0*a.y + c1*b.y);
}

__global__ void k_norm(float* __restrict__ normv){
    int j = blockIdx.x*blockDim.x + threadIdx.x;
    if (j >= OLA_) return;
    float acc = 0.f;
    for (int fr = 0; fr < NFR_; fr++){
        int n = j - fr*HOP_;
        if (n >= 0 && n < 512){
            float w = 0.5f - 0.5f*cosf(6.283185307179586f*(float)n/512.f);
            acc += w*w;
        }
    }
    normv[j] = (acc > 1e-10f) ? acc : 1.f;
}

// ======================= fused STFT/filter/ISTFT ===============================
#define FS_SMEM 61440
__global__ void __launch_bounds__(256)
k_fsru(const float* __restrict__ ecg_bdt, const float2* __restrict__ fbeff,
       const float* __restrict__ normv, const float* __restrict__ gate,
       float* __restrict__ xsum){
    extern __shared__ float sm[];
    float* twR  = sm;
    float* twI  = sm + 512;
    float* win  = sm + 1024;
    float* ola  = sm + 1536;
    float* bufs = sm + 1536 + OLA_;
    int tid = threadIdx.x, g = tid >> 6, t = tid & 63;
    int bd = blockIdx.x, d = bd & (DIM_-1);
    float* AR = bufs + (g*4+0)*576;
    float* AI = bufs + (g*4+1)*576;
    float* BR = bufs + (g*4+2)*576;
    float* BI = bufs + (g*4+3)*576;
    for (int m = tid; m < 512; m += 256){
        float s, c;
        sincosf(6.283185307179586f*(float)m/512.f, &s, &c);
        twR[m] = c; twI[m] = -s;
        win[m] = 0.5f - 0.5f*c;
    }
    for (int j = tid; j < OLA_; j += 256) ola[j] = 0.f;
    const float*  x  = ecg_bdt + (size_t)bd*TLEN_;
    const float2* fe = fbeff + (size_t)d*SLEN_;
    const float sc = 1.f/(256.f*256.f*4369.f);
    __syncthreads();
    for (int rr = 0; rr < 5; rr++){
        int fr = rr*4 + g;
        bool act = (fr < NFR_);
        if (act){
            #pragma unroll
            for (int q = 0; q < 8; q++){
                int idx = t + 64*q;
                int tau = fr*HOP_ + idx - HOP_;
                float v = (tau >= 0 && tau < TLEN_) ? x[tau] : 0.f;
                AR[PHYS(idx)] = v*win[idx]; AI[PHYS(idx)] = 0.f;
            }
        }
        __syncthreads();
        if (act) r8stage<-1,1 >(AR,AI,BR,BI,twR,twI,t);
        __syncthreads();
        if (act) r8stage<-1,8 >(BR,BI,AR,AI,twR,twI,t);
        __syncthreads();
        if (act) r8stage<-1,64>(AR,AI,BR,BI,twR,twI,t);
        __syncthreads();
        if (act){
            #pragma unroll
            for (int q = 0; q < 8; q++){
                int k = t + 64*q; int p = PHYS(k);
                float zr = BR[p], zi = BI[p];
                float z2r = (zr*zr - zi*zi)*sc, z2i = 2.f*zr*zi*sc;
                int m = (k <= 256) ? k : 512 - k;
                float2 f = fe[fr*NB_ + m];
                float fi = (k <= 256) ? f.y : -f.y;
                float yr = z2r*f.x - z2i*fi;
                float yi = z2r*fi + z2i*f.x;
                if (k == 0 || k == 256) yi = 0.f;
                AR[p] = yr; AI[p] = yi;
            }
        }
        __syncthreads();
        if (act) r8stage<1,1 >(AR,AI,BR,BI,twR,twI,t);
        __syncthreads();
        if (act) r8stage<1,8 >(BR,BI,AR,AI,twR,twI,t);
        __syncthreads();
        if (act) r8stage<1,64>(AR,AI,BR,BI,twR,twI,t);
        if (act){
            #pragma unroll
            for (int q = 0; q < 8; q++){
                int n = t + 64*q;
                atomicAdd(&ola[fr*HOP_ + n], BR[PHYS(n)]*0.5f*win[n]);
            }
        }
        __syncthreads();
    }
    float gv = gate[bd];
    float* xo = xsum + (size_t)bd*TLEN_;
    for (int tau = tid; tau < TLEN_; tau += 256){
        int j = tau + HOP_;
        xo[tau] = (ola[j]/normv[j])*gv + x[tau];
    }
}

// ======================= image path ============================================
__global__ void k_imgfft(const float* __restrict__ image, const float2* __restrict__ ifb,
                         float2* __restrict__ Zimg, float c0, float c1){
    int f = blockIdx.x, b = blockIdx.y, d = threadIdx.x;
    __shared__ float cs[NPATCH_], sn[NPATCH_];
    for (int n = d; n < NPATCH_; n += DIM_){
        int m = (f*n) % NPATCH_;
        float s, c;
        sincosf(-6.283185307179586f*(float)m/(float)NPATCH_, &s, &c);
        cs[n] = c; sn[n] = s;
    }
    __syncthreads();
    const float* xb = image + (size_t)b*NPATCH_*DIM_;
    float ar = 0.f, ai = 0.f;
    for (int n = 0; n < NPATCH_; n++){
        float v = xb[n*DIM_ + d];
        ar = fmaf(v, cs[n], ar);
        ai = fmaf(v, sn[n], ai);
    }
    ar *= (1.f/14.f); ai *= (1.f/14.f);
    float2 fa = ifb[((size_t)0*NFREQ_+f)*DIM_ + d];
    float2 fb = ifb[((size_t)1*NFREQ_+f)*DIM_ + d];
    float2 feff = make_float2(c0*fa.x+c1*fb.x, c0*fa.y+c1*fb.y);
    float z2r = (ar*ar - ai*ai)*(1.f/99.f), z2i = 2.f*ar*ai*(1.f/99.f);
    Zimg[((size_t)b*NFREQ_+f)*DIM_ + d] =
        make_float2(z2r*feff.x - z2i*feff.y, z2r*feff.y + z2i*feff.x);
}

__global__ void k_gate(const float2* __restrict__ Zimg, const float2* __restrict__ sel,
                       const float* __restrict__ w, const float* __restrict__ bias,
                       float* __restrict__ gate){
    int b = blockIdx.x, d = threadIdx.x;
    __shared__ float g[DIM_];
    float acc = 0.f;
    for (int f = 0; f < NFREQ_; f++){
        float2 z = Zimg[((size_t)b*NFREQ_+f)*DIM_ + d];
        float2 s = sel[(size_t)f*DIM_ + d];
        acc += z.x*s.x - z.y*s.y;
    }
    g[d] = acc*(1.f/99.f);
    __syncthreads();
    float o = bias[d];
    for (int k = 0; k < DIM_; k++) o = fmaf(g[k], w[d*DIM_+k], o);
    gate[b*DIM_+d] = o;
}

__global__ void k_imgirfft(const float2* __restrict__ Zimg, const float* __restrict__ image,
                           float* __restrict__ ximg){
    int n = blockIdx.x, b = blockIdx.y, d = threadIdx.x;
    __shared__ float cs[NFREQ_], sn[NFREQ_];
    for (int f = d; f < NFREQ_; f += DIM_){
        int m = (f*n) % NPATCH_;
        float s, c;
        sincosf(6.283185307179586f*(float)m/(float)NPATCH_, &s, &c);
        cs[f] = c; sn[f] = s;
    }
    __syncthreads();
    const float2* Zb = Zimg + (size_t)b*NFREQ_*DIM_;
    float acc = 0.f;
    #pragma unroll 4
    for (int f = 0; f < NFREQ_; f++){
        float wgt = (f == 0 || f == NFREQ_-1) ? 1.f : 2.f;
        float2 z = Zb[f*DIM_ + d];
        acc += wgt*(z.x*cs[f] - z.y*sn[f]);
    }
    size_t idx = ((size_t)b*NPATCH_ + n)*DIM_ + d;
    ximg[idx] = acc*(1.f/14.f) + image[idx];
}

// ======================= wmma tf32 AddNorm =====================================
// 128 rows per block, 256 threads (8 warps as 4x2). smem: X | H | B, each 128x136.
#define LDM_ 136
#define AW_SMEM (3*128*LDM_*4)

__global__ void __launch_bounds__(256)
k_addnorm_w(const float* __restrict__ xin, float* __restrict__ out, int trans,
            const float* __restrict__ g1, const float* __restrict__ b1,
            const float* __restrict__ w1, const float* __restrict__ bb1,
            const float* __restrict__ w2, const float* __restrict__ bb2,
            const float* __restrict__ g2, const float* __restrict__ b2){
    extern __shared__ float sm[];
    float* X = sm;                    // post-LN1 x (A operand + residual)
    float* H = sm + 128*LDM_;         // gelu output (A operand of GEMM2)
    float* Bm = sm + 2*128*LDM_;      // w1 -> w2 -> C2
    const int tid = threadIdx.x, warp = tid>>5, lane = tid&31;
    const int wm = warp >> 1, wn = warp & 1;   // warp tile: rows wm*32, cols wn*64

    size_t row0 = (size_t)blockIdx.x * 128;
    if (trans){
        int b = (int)(row0 >> 12), tok0 = (int)(row0 & 4095);
        const float* xb = xin + ((size_t)b*DIM_)*TLEN_ + tok0;
        for (int i = tid; i < 128*128; i += 256){
            int dd = i >> 7, tok = i & 127;
            X[tok*LDM_ + dd] = xb[(size_t)dd*TLEN_ + tok];
        }
    } else {
        const float* xb = xin + row0*DIM_;
        for (int i = tid; i < 128*128; i += 256)
            X[(i>>7)*LDM_ + (i&127)] = xb[i];
    }
    for (int i = tid; i < 128*128; i += 256)
        Bm[(i>>7)*LDM_ + (i&127)] = w1[i];
    __syncthreads();

    // LN1: 8 warps x 16 rows; in-place in X
    float gv[4], bv[4];
    #pragma unroll
    for (int j = 0; j < 4; j++){ gv[j] = g1[lane+32*j]; bv[j] = b1[lane+32*j]; }
    for (int rr = 0; rr < 16; rr++){
        int r = warp*16 + rr;
        float v[4];
        #pragma unroll
        for (int j = 0; j < 4; j++) v[j] = X[r*LDM_ + lane+32*j];
        float s = v[0]+v[1]+v[2]+v[3];
        #pragma unroll
        for (int o = 16; o; o >>= 1) s += __shfl_xor_sync(0xffffffffu, s, o);
        float mn = s*(1.f/128.f), q = 0.f;
        #pragma unroll
        for (int j = 0; j < 4; j++){ v[j] -= mn; q += v[j]*v[j]; }
        #pragma unroll
        for (int o = 16; o; o >>= 1) q += __shfl_xor_sync(0xffffffffu, q, o);
        float inv = rsqrtf(q*(1.f/128.f) + 1e-5f);
        #pragma unroll
        for (int j = 0; j < 4; j++)
            X[r*LDM_ + lane+32*j] = v[j]*inv*gv[j] + bv[j];
    }
    __syncthreads();

    // GEMM1: H = X @ w1
    wmma::fragment<wmma::accumulator, 16, 16, 8, float> acc[2][4];
    #pragma unroll
    for (int i = 0; i < 2; i++)
        #pragma unroll
        for (int j = 0; j < 4; j++) wmma::fill_fragment(acc[i][j], 0.f);
    for (int kk = 0; kk < 128; kk += 8){
        wmma::fragment<wmma::matrix_a, 16, 16, 8, wmma::precision::tf32, wmma::row_major> af[2];
        wmma::fragment<wmma::matrix_b, 16, 16, 8, wmma::precision::tf32, wmma::row_major> bf[4];
        #pragma unroll
        for (int i = 0; i < 2; i++){
            wmma::load_matrix_sync(af[i], X + (wm*32 + i*16)*LDM_ + kk, LDM_);
            #pragma unroll
            for (int e = 0; e < af[i].num_elements; e++)
                af[i].x[e] = wmma::__float_to_tf32(af[i].x[e]);
        }
        #pragma unroll
        for (int j = 0; j < 4; j++){
            wmma::load_matrix_sync(bf[j], Bm + kk*LDM_ + wn*64 + j*16, LDM_);
            #pragma unroll
            for (int e = 0; e < bf[j].num_elements; e++)
                bf[j].x[e] = wmma::__float_to_tf32(bf[j].x[e]);
        }
        #pragma unroll
        for (int i = 0; i < 2; i++)
            #pragma unroll
            for (int j = 0; j < 4; j++)
                wmma::mma_sync(acc[i][j], af[i], bf[j], acc[i][j]);
    }
    #pragma unroll
    for (int i = 0; i < 2; i++)
        #pragma unroll
        for (int j = 0; j < 4; j++)
            wmma::store_matrix_sync(H + (wm*32 + i*16)*LDM_ + wn*64 + j*16,
                                    acc[i][j], LDM_, wmma::mem_row_major);
    __syncthreads();

    // gelu(H + bb1) in place ; and overwrite Bm with w2
    for (int i = tid; i < 128*128; i += 256){
        int r = i >> 7, c = i & 127;
        float h = H[r*LDM_ + c] + bb1[c];
        H[r*LDM_ + c] = 0.5f*h*(1.f + erff(h*0.70710678118654752f));
        Bm[r*LDM_ + c] = w2[i];
    }
    __syncthreads();

    // GEMM2: C2 = H @ w2
    #pragma unroll
    for (int i = 0; i < 2; i++)
        #pragma unroll
        for (int j = 0; j < 4; j++) wmma::fill_fragment(acc[i][j], 0.f);
    for (int kk = 0; kk < 128; kk += 8){
        wmma::fragment<wmma::matrix_a, 16, 16, 8, wmma::precision::tf32, wmma::row_major> af[2];
        wmma::fragment<wmma::matrix_b, 16, 16, 8, wmma::precision::tf32, wmma::row_major> bf[4];
        #pragma unroll
        for (int i = 0; i < 2; i++){
            wmma::load_matrix_sync(af[i], H + (wm*32 + i*16)*LDM_ + kk, LDM_);
            #pragma unroll
            for (int e = 0; e < af[i].num_elements; e++)
                af[i].x[e] = wmma::__float_to_tf32(af[i].x[e]);
        }
        #pragma unroll
        for (int j = 0; j < 4; j++){
            wmma::load_matrix_sync(bf[j], Bm + kk*LDM_ + wn*64 + j*16, LDM_);
            #pragma unroll
            for (int e = 0; e < bf[j].num_elements; e++)
                bf[j].x[e] = wmma::__float_to_tf32(bf[j].x[e]);
        }
        #pragma unroll
        for (int i = 0; i < 2; i++)
            #pragma unroll
            for (int j = 0; j < 4; j++)
                wmma::mma_sync(acc[i][j], af[i], bf[j], acc[i][j]);
    }
    __syncthreads();    // all warps done reading Bm before overwrite
    #pragma unroll
    for (int i = 0; i < 2; i++)
        #pragma unroll
        for (int j = 0; j < 4; j++)
            wmma::store_matrix_sync(Bm + (wm*32 + i*16)*LDM_ + wn*64 + j*16,
                                    acc[i][j], LDM_, wmma::mem_row_major);
    __syncthreads();

    // residual + LN2 -> out
    #pragma unroll
    for (int j = 0; j < 4; j++){ gv[j] = g2[lane+32*j]; bv[j] = b2[lane+32*j]; }
    for (int rr = 0; rr < 16; rr++){
        int r = warp*16 + rr;
        float v[4];
        #pragma unroll
        for (int j = 0; j < 4; j++){
            int c = lane + 32*j;
            v[j] = Bm[r*LDM_ + c] + bb2[c] + X[r*LDM_ + c];
        }
        float s = v[0]+v[1]+v[2]+v[3];
        #pragma unroll
        for (int o = 16; o; o >>= 1) s += __shfl_xor_sync(0xffffffffu, s, o);
        float mn = s*(1.f/128.f), q = 0.f;
        #pragma unroll
        for (int j = 0; j < 4; j++){ v[j] -= mn; q += v[j]*v[j]; }
        #pragma unroll
        for (int o = 16; o; o >>= 1) q += __shfl_xor_sync(0xffffffffu, q, o);
        float inv = rsqrtf(q*(1.f/128.f) + 1e-5f);
        #pragma unroll
        for (int j = 0; j < 4; j++)
            out[(row0 + r)*DIM_ + lane+32*j] = v[j]*inv*gv[j] + bv[j];
    }
}

// ======================= launch ================================================
extern "C" void kernel_launch(void* const* d_in, const int* in_sizes, int n_in,
                              void* d_out, int out_size){
    (void)in_sizes; (void)n_in; (void)out_size;
    const float* ecg     = (const float*)d_in[0];
    const float* image   = (const float*)d_in[1];
    const float* tfb     = (const float*)d_in[2];
    const float* ifb     = (const float*)d_in[3];
    const float* i2t_sel = (const float*)d_in[4];
    const float* i2t_w   = (const float*)d_in[5];
    const float* i2t_b   = (const float*)d_in[6];
    const float* t_ln1_g = (const float*)d_in[7];
    const float* t_ln1_b = (const float*)d_in[8];
    const float* t_w1    = (const float*)d_in[9];
    const float* t_b1    = (const float*)d_in[10];
    const float* t_w2    = (const float*)d_in[11];
    const float* t_b2    = (const float*)d_in[12];
    const float* t_ln2_g = (const float*)d_in[13];
    const float* t_ln2_b = (const float*)d_in[14];
    const float* i_ln1_g = (const float*)d_in[15];
    const float* i_ln1_b = (const float*)d_in[16];
    const float* i_w1    = (const float*)d_in[17];
    const float* i_b1    = (const float*)d_in[18];
    const float* i_w2    = (const float*)d_in[19];
    const float* i_b2    = (const float*)d_in[20];
    const float* i_ln2_g = (const float*)d_in[21];
    const float* i_ln2_b = (const float*)d_in[22];

    void* p;
    cudaGetSymbolAddress(&p, g_ecg_bdt);  float*  ecg_bdt = (float*)p;
    cudaGetSymbolAddress(&p, g_xsum_bdt); float*  xsum    = (float*)p;
    cudaGetSymbolAddress(&p, g_fbeff);    float2* fbeff   = (float2*)p;
    cudaGetSymbolAddress(&p, g_Zimg);     float2* Zimg    = (float2*)p;
    cudaGetSymbolAddress(&p, g_gate);     float*  gate    = (float*)p;
    cudaGetSymbolAddress(&p, g_ximg);     float*  ximg    = (float*)p;
    cudaGetSymbolAddress(&p, g_normv);    float*  normv   = (float*)p;

    float c0 = cosf(1.f*3.1415926f);
    float c1 = cosf(3.f*3.1415926f);

    cudaFuncSetAttribute(k_fsru, cudaFuncAttributeMaxDynamicSharedMemorySize, FS_SMEM);
    cudaFuncSetAttribute(k_addnorm_w, cudaFuncAttributeMaxDynamicSharedMemorySize, AW_SMEM);

    float* text_out = (float*)d_out;
    float* img_out  = (float*)d_out + (size_t)BATCH_*TLEN_*DIM_;

    k_transpose<<<dim3(DIM_/32, TLEN_/32, BATCH_), dim3(32,8)>>>(ecg, ecg_bdt, TLEN_, DIM_);
    k_fbeff<<<SLEN_, DIM_>>>((const float2*)tfb, fbeff, c0, c1);
    k_norm<<<(OLA_+255)/256, 256>>>(normv);
    k_imgfft<<<dim3(NFREQ_, BATCH_), DIM_>>>(image, (const float2*)ifb, Zimg, c0, c1);
    k_gate<<<BATCH_, DIM_>>>(Zimg, (const float2*)i2t_sel, i2t_w, i2t_b, gate);
    k_fsru<<<BATCH_*DIM_, 256, FS_SMEM>>>(ecg_bdt, fbeff, normv, gate, xsum);
    k_addnorm_w<<<(BATCH_*TLEN_)/128, 256, AW_SMEM>>>(xsum, text_out, 1,
        t_ln1_g, t_ln1_b, t_w1, t_b1, t_w2, t_b2, t_ln2_g, t_ln2_b);
    k_imgirfft<<<dim3(NPATCH_, BATCH_), DIM_>>>(Zimg, image, ximg);
    k_addnorm_w<<<(BATCH_*NPATCH_)/128, 256, AW_SMEM>>>(ximg, img_out, 0,
        i_ln1_g, i_ln1_b, i_w1, i_b1, i_w2, i_b2, i_ln2_g, i_ln2_b);
}

// round 8
// speedup vs baseline: 1.6119x; 1.1694x over previous
#include <cuda_runtime.h>
#include <math.h>
#include <stdint.h>
#include <mma.h>
using namespace nvcuda;

#define BATCH_  32
#define DIM_    128
#define TLEN_   4096
#define HOP_    256
#define NFR_    17
#define NB_     257
#define SLEN_   4369
#define NPATCH_ 196
#define NFREQ_  99
#define OLA_    4608

static __device__ float  g_ecg_bdt[BATCH_*DIM_*TLEN_];
static __device__ float  g_xsum_bdt[BATCH_*DIM_*TLEN_];
static __device__ float2 g_fbeff  [DIM_*SLEN_];
static __device__ float2 g_Zimg   [BATCH_*NFREQ_*DIM_];
static __device__ float  g_gate   [BATCH_*DIM_];
static __device__ float  g_ximg   [BATCH_*NPATCH_*DIM_];
static __device__ float  g_normv  [OLA_];

// ======================= radix-8 FFT =======================
template<int SIGN>
__device__ __forceinline__ void fft8(float* r, float* i){
    const float c = 0.70710678118654752f;
    float ur[4], ui[4], vr[4], vi[4];
    #pragma unroll
    for (int q = 0; q < 4; q++){
        ur[q] = r[q] + r[q+4]; ui[q] = i[q] + i[q+4];
        vr[q] = r[q] - r[q+4]; vi[q] = i[q] - i[q+4];
    }
    { float x = vr[1], y = vi[1];
      if (SIGN < 0){ vr[1] = c*(x+y); vi[1] = c*(y-x); }
      else         { vr[1] = c*(x-y); vi[1] = c*(x+y); } }
    { float x = vr[2], y = vi[2];
      if (SIGN < 0){ vr[2] = y;  vi[2] = -x; }
      else         { vr[2] = -y; vi[2] = x;  } }
    { float x = vr[3], y = vi[3];
      if (SIGN < 0){ vr[3] = c*(y-x);  vi[3] = -c*(x+y); }
      else         { vr[3] = -c*(x+y); vi[3] = c*(x-y);  } }
    float p0r = ur[0]+ur[2], p0i = ui[0]+ui[2];
    float p2r = ur[0]-ur[2], p2i = ui[0]-ui[2];
    float p1r = ur[1]+ur[3], p1i = ui[1]+ui[3];
    float t3r = ur[1]-ur[3], t3i = ui[1]-ui[3];
    float p3r, p3i;
    if (SIGN < 0){ p3r = t3i; p3i = -t3r; } else { p3r = -t3i; p3i = t3r; }
    float q0r = vr[0]+vr[2], q0i = vi[0]+vi[2];
    float q2r = vr[0]-vr[2], q2i = vi[0]-vi[2];
    float q1r = vr[1]+vr[3], q1i = vi[1]+vi[3];
    float s3r = vr[1]-vr[3], s3i = vi[1]-vi[3];
    float q3r, q3i;
    if (SIGN < 0){ q3r = s3i; q3i = -s3r; } else { q3r = -s3i; q3i = s3r; }
    r[0] = p0r+p1r; i[0] = p0i+p1i;
    r[1] = p0r-p1r; i[1] = p0i-p1i;
    r[2] = p2r+p3r; i[2] = p2i+p3i;
    r[3] = p2r-p3r; i[3] = p2i-p3i;
    r[4] = q0r+q1r; i[4] = q0i+q1i;
    r[5] = q0r-q1r; i[5] = q0i-q1i;
    r[6] = q2r+q3r; i[6] = q2i+q3i;
    r[7] = q2r-q3r; i[7] = q2i-q3i;
}

#define PHYS(idx) ((idx) + ((idx) >> 3))

template<int SIGN, int S>
__device__ __forceinline__ void r8stage(const float* __restrict__ sR,
                                        const float* __restrict__ sI,
                                        float* __restrict__ dR,
                                        float* __restrict__ dI,
                                        const float* __restrict__ twR,
                                        const float* __restrict__ twI, int t){
    float xr[8], xi[8];
    #pragma unroll
    for (int q = 0; q < 8; q++){
        int idx = t + 64*q;
        xr[q] = sR[PHYS(idx)]; xi[q] = sI[PHYS(idx)];
    }
    fft8<SIGN>(xr, xi);
    const int brev[8] = {0,4,2,6,1,5,3,7};
    int hi = t / S, lo = t % S;
    int base = hi*8*S + lo;
    int tb = hi*S;
    #pragma unroll
    for (int j = 0; j < 8; j++){
        float yr = xr[brev[j]], yi = xi[brev[j]];
        int m = (tb*j) & 511;
        float wr = twR[m];
        float wi = (SIGN < 0) ? twI[m] : -twI[m];
        int idx = base + j*S;
        dR[PHYS(idx)] = yr*wr - yi*wi;
        dI[PHYS(idx)] = yr*wi + yi*wr;
    }
}

// group barrier: 64 threads (2 warps), ids 1..4
__device__ __forceinline__ void gbar(int id){
    asm volatile("bar.sync %0, %1;" :: "r"(id), "r"(64) : "memory");
}

// ======================= small kernels =========================================
__global__ void k_transpose(const float* __restrict__ in, float* __restrict__ out,
                            int R, int C){
    __shared__ float tile[32][33];
    size_t base = (size_t)blockIdx.z * R * C;
    int c0 = blockIdx.x*32, r0 = blockIdx.y*32;
    int tx = threadIdx.x, ty = threadIdx.y;
    #pragma unroll
    for (int k = 0; k < 32; k += 8)
        tile[ty+k][tx] = in[base + (size_t)(r0+ty+k)*C + c0+tx];
    __syncthreads();
    #pragma unroll
    for (int k = 0; k < 32; k += 8)
        out[base + (size_t)(c0+ty+k)*R + r0+tx] = tile[tx][ty+k];
}

__global__ void k_fbeff(const float2* __restrict__ tfb, float2* __restrict__ fbeff,
                        float c0, float c1){
    int s = blockIdx.x, d = threadIdx.x;
    int k = s / NFR_, fr = s % NFR_;
    float2 a = tfb[(size_t)s*DIM_ + d];
    float2 b = tfb[((size_t)SLEN_+s)*DIM_ + d];
    fbeff[(size_t)d*SLEN_ + fr*NB_ + k] =
        make_float2(c0*a.x + c1*b.x, c0*a.y + c1*b.y);
}

__global__ void k_norm(float* __restrict__ normv){
    int j = blockIdx.x*blockDim.x + threadIdx.x;
    if (j >= OLA_) return;
    float acc = 0.f;
    for (int fr = 0; fr < NFR_; fr++){
        int n = j - fr*HOP_;
        if (n >= 0 && n < 512){
            float w = 0.5f - 0.5f*cosf(6.283185307179586f*(float)n/512.f);
            acc += w*w;
        }
    }
    normv[j] = (acc > 1e-10f) ? acc : 1.f;
}

// ======================= fused STFT/filter/ISTFT (paired real FFT) =============
#define FS_SMEM 61440
__global__ void __launch_bounds__(256)
k_fsru(const float* __restrict__ ecg_bdt, const float2* __restrict__ fbeff,
       const float* __restrict__ normv, const float* __restrict__ gate,
       float* __restrict__ xsum){
    extern __shared__ float sm[];
    float* twR  = sm;
    float* twI  = sm + 512;
    float* win  = sm + 1024;
    float* ola  = sm + 1536;
    float* bufs = sm + 1536 + OLA_;
    int tid = threadIdx.x, g = tid >> 6, t = tid & 63;
    int bd = blockIdx.x, d = bd & (DIM_-1);
    float* AR = bufs + (g*4+0)*576;
    float* AI = bufs + (g*4+1)*576;
    float* BR = bufs + (g*4+2)*576;
    float* BI = bufs + (g*4+3)*576;
    for (int m = tid; m < 512; m += 256){
        float s, c;
        sincosf(6.283185307179586f*(float)m/512.f, &s, &c);
        twR[m] = c; twI[m] = -s;
        win[m] = 0.5f - 0.5f*c;
    }
    for (int j = tid; j < OLA_; j += 256) ola[j] = 0.f;
    const float*  x  = ecg_bdt + (size_t)bd*TLEN_;
    const float2* fe = fbeff + (size_t)d*SLEN_;
    const float sc = 1.f/(256.f*256.f*4369.f);
    const int bid = g + 1;
    __syncthreads();

    // 3 rounds: rr<2 -> pair (8rr+2g, 8rr+2g+1); rr==2 -> group 0 does frame 16
    for (int rr = 0; rr < 3; rr++){
        int fr_a, fr_b; bool act;
        if (rr < 2){ fr_a = 8*rr + 2*g; fr_b = fr_a + 1; act = true; }
        else       { fr_a = 16; fr_b = -1; act = (g == 0); }
        if (!act) continue;
        bool hasb = (fr_b >= 0);
        // load two windowed frames packed as a + i b
        #pragma unroll
        for (int q = 0; q < 8; q++){
            int idx = t + 64*q;
            int ta = fr_a*HOP_ + idx - HOP_;
            float va = (ta >= 0 && ta < TLEN_) ? x[ta] : 0.f;
            float vb = 0.f;
            if (hasb){
                int tb2 = fr_b*HOP_ + idx - HOP_;
                vb = (tb2 >= 0 && tb2 < TLEN_) ? x[tb2] : 0.f;
            }
            AR[PHYS(idx)] = va*win[idx]; AI[PHYS(idx)] = vb*win[idx];
        }
        gbar(bid);
        r8stage<-1,1 >(AR,AI,BR,BI,twR,twI,t);
        gbar(bid);
        r8stage<-1,8 >(BR,BI,AR,AI,twR,twI,t);
        gbar(bid);
        r8stage<-1,64>(AR,AI,BR,BI,twR,twI,t);
        gbar(bid);
        // split A/B spectra, filter both, merge C = Ya + i*Yb into AR/AI
        #pragma unroll
        for (int q = 0; q < 8; q++){
            int k = t + 64*q;
            int km = (512 - k) & 511;
            float Zkr = BR[PHYS(k)],  Zki = BI[PHYS(k)];
            float Zmr = BR[PHYS(km)], Zmi = BI[PHYS(km)];
            float Ar  = 0.5f*(Zkr + Zmr), Aii = 0.5f*(Zki - Zmi);
            float Brr = 0.5f*(Zki + Zmi), Bii = 0.5f*(Zmr - Zkr);
            int m = (k <= 256) ? k : 512 - k;
            float sgn = (k <= 256) ? 1.f : -1.f;
            float2 fa = fe[fr_a*NB_ + m];
            float fai = sgn*fa.y;
            float a2r = (Ar*Ar - Aii*Aii)*sc, a2i = 2.f*Ar*Aii*sc;
            float Yar = a2r*fa.x - a2i*fai;
            float Yai = a2r*fai + a2i*fa.x;
            if (k == 0 || k == 256) Yai = 0.f;
            float Ybr = 0.f, Ybi = 0.f;
            if (hasb){
                float2 fb = fe[fr_b*NB_ + m];
                float fbi = sgn*fb.y;
                float b2r = (Brr*Brr - Bii*Bii)*sc, b2i = 2.f*Brr*Bii*sc;
                Ybr = b2r*fb.x - b2i*fbi;
                Ybi = b2r*fbi + b2i*fb.x;
                if (k == 0 || k == 256) Ybi = 0.f;
            }
            AR[PHYS(k)] = Yar - Ybi;
            AI[PHYS(k)] = Yai + Ybr;
        }
        gbar(bid);
        r8stage<1,1 >(AR,AI,BR,BI,twR,twI,t);
        gbar(bid);
        r8stage<1,8 >(BR,BI,AR,AI,twR,twI,t);
        gbar(bid);
        r8stage<1,64>(AR,AI,BR,BI,twR,twI,t);
        // final stage wrote exactly the positions this thread reads below
        #pragma unroll
        for (int q = 0; q < 8; q++){
            int n = t + 64*q;
            float wn = 0.5f*win[n];
            atomicAdd(&ola[fr_a*HOP_ + n], BR[PHYS(n)]*wn);
            if (hasb) atomicAdd(&ola[fr_b*HOP_ + n], BI[PHYS(n)]*wn);
        }
    }
    __syncthreads();
    float gv = gate[bd];
    float* xo = xsum + (size_t)bd*TLEN_;
    for (int tau = tid; tau < TLEN_; tau += 256){
        int j = tau + HOP_;
        xo[tau] = (ola[j]/normv[j])*gv + x[tau];
    }
}

// ======================= image path ============================================
__global__ void k_imgfft(const float* __restrict__ image, const float2* __restrict__ ifb,
                         float2* __restrict__ Zimg, float c0, float c1){
    int f = blockIdx.x, b = blockIdx.y, d = threadIdx.x;
    __shared__ float cs[NPATCH_], sn[NPATCH_];
    for (int n = d; n < NPATCH_; n += DIM_){
        int m = (f*n) % NPATCH_;
        float s, c;
        sincosf(-6.283185307179586f*(float)m/(float)NPATCH_, &s, &c);
        cs[n] = c; sn[n] = s;
    }
    __syncthreads();
    const float* xb = image + (size_t)b*NPATCH_*DIM_;
    float ar = 0.f, ai = 0.f;
    for (int n = 0; n < NPATCH_; n++){
        float v = xb[n*DIM_ + d];
        ar = fmaf(v, cs[n], ar);
        ai = fmaf(v, sn[n], ai);
    }
    ar *= (1.f/14.f); ai *= (1.f/14.f);
    float2 fa = ifb[((size_t)0*NFREQ_+f)*DIM_ + d];
    float2 fb = ifb[((size_t)1*NFREQ_+f)*DIM_ + d];
    float2 feff = make_float2(c0*fa.x+c1*fb.x, c0*fa.y+c1*fb.y);
    float z2r = (ar*ar - ai*ai)*(1.f/99.f), z2i = 2.f*ar*ai*(1.f/99.f);
    Zimg[((size_t)b*NFREQ_+f)*DIM_ + d] =
        make_float2(z2r*feff.x - z2i*feff.y, z2r*feff.y + z2i*feff.x);
}

__global__ void k_gate(const float2* __restrict__ Zimg, const float2* __restrict__ sel,
                       const float* __restrict__ w, const float* __restrict__ bias,
                       float* __restrict__ gate){
    int b = blockIdx.x, d = threadIdx.x;
    __shared__ float g[DIM_];
    float acc = 0.f;
    for (int f = 0; f < NFREQ_; f++){
        float2 z = Zimg[((size_t)b*NFREQ_+f)*DIM_ + d];
        float2 s = sel[(size_t)f*DIM_ + d];
        acc += z.x*s.x - z.y*s.y;
    }
    g[d] = acc*(1.f/99.f);
    __syncthreads();
    float o = bias[d];
    for (int k = 0; k < DIM_; k++) o = fmaf(g[k], w[d*DIM_+k], o);
    gate[b*DIM_+d] = o;
}

__global__ void k_imgirfft(const float2* __restrict__ Zimg, const float* __restrict__ image,
                           float* __restrict__ ximg){
    int n = blockIdx.x, b = blockIdx.y, d = threadIdx.x;
    __shared__ float cs[NFREQ_], sn[NFREQ_];
    for (int f = d; f < NFREQ_; f += DIM_){
        int m = (f*n) % NPATCH_;
        float s, c;
        sincosf(6.283185307179586f*(float)m/(float)NPATCH_, &s, &c);
        cs[f] = c; sn[f] = s;
    }
    __syncthreads();
    const float2* Zb = Zimg + (size_t)b*NFREQ_*DIM_;
    float acc = 0.f;
    #pragma unroll 4
    for (int f = 0; f < NFREQ_; f++){
        float wgt = (f == 0 || f == NFREQ_-1) ? 1.f : 2.f;
        float2 z = Zb[f*DIM_ + d];
        acc += wgt*(z.x*cs[f] - z.y*sn[f]);
    }
    size_t idx = ((size_t)b*NPATCH_ + n)*DIM_ + d;
    ximg[idx] = acc*(1.f/14.f) + image[idx];
}

// ======================= wmma tf32 AddNorm =====================================
#define LDM_ 136
#define AW_SMEM (3*128*LDM_*4)

__global__ void __launch_bounds__(256)
k_addnorm_w(const float* __restrict__ xin, float* __restrict__ out, int trans,
            const float* __restrict__ g1, const float* __restrict__ b1,
            const float* __restrict__ w1, const float* __restrict__ bb1,
            const float* __restrict__ w2, const float* __restrict__ bb2,
            const float* __restrict__ g2, const float* __restrict__ b2){
    extern __shared__ float sm[];
    float* X = sm;
    float* H = sm + 128*LDM_;
    float* Bm = sm + 2*128*LDM_;
    const int tid = threadIdx.x, warp = tid>>5, lane = tid&31;
    const int wm = warp >> 1, wn = warp & 1;

    size_t row0 = (size_t)blockIdx.x * 128;
    if (trans){
        int b = (int)(row0 >> 12), tok0 = (int)(row0 & 4095);
        const float* xb = xin + ((size_t)b*DIM_)*TLEN_ + tok0;
        for (int i = tid; i < 128*128; i += 256){
            int dd = i >> 7, tok = i & 127;
            X[tok*LDM_ + dd] = xb[(size_t)dd*TLEN_ + tok];
        }
    } else {
        const float* xb = xin + row0*DIM_;
        for (int i = tid; i < 128*128; i += 256)
            X[(i>>7)*LDM_ + (i&127)] = xb[i];
    }
    for (int i = tid; i < 128*128; i += 256)
        Bm[(i>>7)*LDM_ + (i&127)] = w1[i];
    __syncthreads();

    float gv[4], bv[4];
    #pragma unroll
    for (int j = 0; j < 4; j++){ gv[j] = g1[lane+32*j]; bv[j] = b1[lane+32*j]; }
    for (int rr = 0; rr < 16; rr++){
        int r = warp*16 + rr;
        float v[4];
        #pragma unroll
        for (int j = 0; j < 4; j++) v[j] = X[r*LDM_ + lane+32*j];
        float s = v[0]+v[1]+v[2]+v[3];
        #pragma unroll
        for (int o = 16; o; o >>= 1) s += __shfl_xor_sync(0xffffffffu, s, o);
        float mn = s*(1.f/128.f), q = 0.f;
        #pragma unroll
        for (int j = 0; j < 4; j++){ v[j] -= mn; q += v[j]*v[j]; }
        #pragma unroll
        for (int o = 16; o; o >>= 1) q += __shfl_xor_sync(0xffffffffu, q, o);
        float inv = rsqrtf(q*(1.f/128.f) + 1e-5f);
        #pragma unroll
        for (int j = 0; j < 4; j++)
            X[r*LDM_ + lane+32*j] = v[j]*inv*gv[j] + bv[j];
    }
    __syncthreads();

    wmma::fragment<wmma::accumulator, 16, 16, 8, float> acc[2][4];
    #pragma unroll
    for (int i = 0; i < 2; i++)
        #pragma unroll
        for (int j = 0; j < 4; j++) wmma::fill_fragment(acc[i][j], 0.f);
    for (int kk = 0; kk < 128; kk += 8){
        wmma::fragment<wmma::matrix_a, 16, 16, 8, wmma::precision::tf32, wmma::row_major> af[2];
        wmma::fragment<wmma::matrix_b, 16, 16, 8, wmma::precision::tf32, wmma::row_major> bf[4];
        #pragma unroll
        for (int i = 0; i < 2; i++){
            wmma::load_matrix_sync(af[i], X + (wm*32 + i*16)*LDM_ + kk, LDM_);
            #pragma unroll
            for (int e = 0; e < af[i].num_elements; e++)
                af[i].x[e] = wmma::__float_to_tf32(af[i].x[e]);
        }
        #pragma unroll
        for (int j = 0; j < 4; j++){
            wmma::load_matrix_sync(bf[j], Bm + kk*LDM_ + wn*64 + j*16, LDM_);
            #pragma unroll
            for (int e = 0; e < bf[j].num_elements; e++)
                bf[j].x[e] = wmma::__float_to_tf32(bf[j].x[e]);
        }
        #pragma unroll
        for (int i = 0; i < 2; i++)
            #pragma unroll
            for (int j = 0; j < 4; j++)
                wmma::mma_sync(acc[i][j], af[i], bf[j], acc[i][j]);
    }
    #pragma unroll
    for (int i = 0; i < 2; i++)
        #pragma unroll
        for (int j = 0; j < 4; j++)
            wmma::store_matrix_sync(H + (wm*32 + i*16)*LDM_ + wn*64 + j*16,
                                    acc[i][j], LDM_, wmma::mem_row_major);
    __syncthreads();

    for (int i = tid; i < 128*128; i += 256){
        int r = i >> 7, c = i & 127;
        float h = H[r*LDM_ + c] + bb1[c];
        H[r*LDM_ + c] = 0.5f*h*(1.f + erff(h*0.70710678118654752f));
        Bm[r*LDM_ + c] = w2[i];
    }
    __syncthreads();

    #pragma unroll
    for (int i = 0; i < 2; i++)
        #pragma unroll
        for (int j = 0; j < 4; j++) wmma::fill_fragment(acc[i][j], 0.f);
    for (int kk = 0; kk < 128; kk += 8){
        wmma::fragment<wmma::matrix_a, 16, 16, 8, wmma::precision::tf32, wmma::row_major> af[2];
        wmma::fragment<wmma::matrix_b, 16, 16, 8, wmma::precision::tf32, wmma::row_major> bf[4];
        #pragma unroll
        for (int i = 0; i < 2; i++){
            wmma::load_matrix_sync(af[i], H + (wm*32 + i*16)*LDM_ + kk, LDM_);
            #pragma unroll
            for (int e = 0; e < af[i].num_elements; e++)
                af[i].x[e] = wmma::__float_to_tf32(af[i].x[e]);
        }
        #pragma unroll
        for (int j = 0; j < 4; j++){
            wmma::load_matrix_sync(bf[j], Bm + kk*LDM_ + wn*64 + j*16, LDM_);
            #pragma unroll
            for (int e = 0; e < bf[j].num_elements; e++)
                bf[j].x[e] = wmma::__float_to_tf32(bf[j].x[e]);
        }
        #pragma unroll
        for (int i = 0; i < 2; i++)
            #pragma unroll
            for (int j = 0; j < 4; j++)
                wmma::mma_sync(acc[i][j], af[i], bf[j], acc[i][j]);
    }
    __syncthreads();
    #pragma unroll
    for (int i = 0; i < 2; i++)
        #pragma unroll
        for (int j = 0; j < 4; j++)
            wmma::store_matrix_sync(Bm + (wm*32 + i*16)*LDM_ + wn*64 + j*16,
                                    acc[i][j], LDM_, wmma::mem_row_major);
    __syncthreads();

    #pragma unroll
    for (int j = 0; j < 4; j++){ gv[j] = g2[lane+32*j]; bv[j] = b2[lane+32*j]; }
    for (int rr = 0; rr < 16; rr++){
        int r = warp*16 + rr;
        float v[4];
        #pragma unroll
        for (int j = 0; j < 4; j++){
            int c = lane + 32*j;
            v[j] = Bm[r*LDM_ + c] + bb2[c] + X[r*LDM_ + c];
        }
        float s = v[0]+v[1]+v[2]+v[3];
        #pragma unroll
        for (int o = 16; o; o >>= 1) s += __shfl_xor_sync(0xffffffffu, s, o);
        float mn = s*(1.f/128.f), q = 0.f;
        #pragma unroll
        for (int j = 0; j < 4; j++){ v[j] -= mn; q += v[j]*v[j]; }
        #pragma unroll
        for (int o = 16; o; o >>= 1) q += __shfl_xor_sync(0xffffffffu, q, o);
        float inv = rsqrtf(q*(1.f/128.f) + 1e-5f);
        #pragma unroll
        for (int j = 0; j < 4; j++)
            out[(row0 + r)*DIM_ + lane+32*j] = v[j]*inv*gv[j] + bv[j];
    }
}

// ======================= launch ================================================
extern "C" void kernel_launch(void* const* d_in, const int* in_sizes, int n_in,
                              void* d_out, int out_size){
    (void)in_sizes; (void)n_in; (void)out_size;
    const float* ecg     = (const float*)d_in[0];
    const float* image   = (const float*)d_in[1];
    const float* tfb     = (const float*)d_in[2];
    const float* ifb     = (const float*)d_in[3];
    const float* i2t_sel = (const float*)d_in[4];
    const float* i2t_w   = (const float*)d_in[5];
    const float* i2t_b   = (const float*)d_in[6];
    const float* t_ln1_g = (const float*)d_in[7];
    const float* t_ln1_b = (const float*)d_in[8];
    const float* t_w1    = (const float*)d_in[9];
    const float* t_b1    = (const float*)d_in[10];
    const float* t_w2    = (const float*)d_in[11];
    const float* t_b2    = (const float*)d_in[12];
    const float* t_ln2_g = (const float*)d_in[13];
    const float* t_ln2_b = (const float*)d_in[14];
    const float* i_ln1_g = (const float*)d_in[15];
    const float* i_ln1_b = (const float*)d_in[16];
    const float* i_w1    = (const float*)d_in[17];
    const float* i_b1    = (const float*)d_in[18];
    const float* i_w2    = (const float*)d_in[19];
    const float* i_b2    = (const float*)d_in[20];
    const float* i_ln2_g = (const float*)d_in[21];
    const float* i_ln2_b = (const float*)d_in[22];

    void* p;
    cudaGetSymbolAddress(&p, g_ecg_bdt);  float*  ecg_bdt = (float*)p;
    cudaGetSymbolAddress(&p, g_xsum_bdt); float*  xsum    = (float*)p;
    cudaGetSymbolAddress(&p, g_fbeff);    float2* fbeff   = (float2*)p;
    cudaGetSymbolAddress(&p, g_Zimg);     float2* Zimg    = (float2*)p;
    cudaGetSymbolAddress(&p, g_gate);     float*  gate    = (float*)p;
    cudaGetSymbolAddress(&p, g_ximg);     float*  ximg    = (float*)p;
    cudaGetSymbolAddress(&p, g_normv);    float*  normv   = (float*)p;

    float c0 = cosf(1.f*3.1415926f);
    float c1 = cosf(3.f*3.1415926f);

    cudaFuncSetAttribute(k_fsru, cudaFuncAttributeMaxDynamicSharedMemorySize, FS_SMEM);
    cudaFuncSetAttribute(k_addnorm_w, cudaFuncAttributeMaxDynamicSharedMemorySize, AW_SMEM);

    float* text_out = (float*)d_out;
    float* img_out  = (float*)d_out + (size_t)BATCH_*TLEN_*DIM_;

    k_transpose<<<dim3(DIM_/32, TLEN_/32, BATCH_), dim3(32,8)>>>(ecg, ecg_bdt, TLEN_, DIM_);
    k_fbeff<<<SLEN_, DIM_>>>((const float2*)tfb, fbeff, c0, c1);
    k_norm<<<(OLA_+255)/256, 256>>>(normv);
    k_imgfft<<<dim3(NFREQ_, BATCH_), DIM_>>>(image, (const float2*)ifb, Zimg, c0, c1);
    k_gate<<<BATCH_, DIM_>>>(Zimg, (const float2*)i2t_sel, i2t_w, i2t_b, gate);
    k_fsru<<<BATCH_*DIM_, 256, FS_SMEM>>>(ecg_bdt, fbeff, normv, gate, xsum);
    k_addnorm_w<<<(BATCH_*TLEN_)/128, 256, AW_SMEM>>>(xsum, text_out, 1,
        t_ln1_g, t_ln1_b, t_w1, t_b1, t_w2, t_b2, t_ln2_g, t_ln2_b);
    k_imgirfft<<<dim3(NPATCH_, BATCH_), DIM_>>>(Zimg, image, ximg);
    k_addnorm_w<<<(BATCH_*NPATCH_)/128, 256, AW_SMEM>>>(ximg, img_out, 0,
        i_ln1_g, i_ln1_b, i_w1, i_b1, i_w2, i_b2, i_ln2_g, i_ln2_b);
}

// round 9
// speedup vs baseline: 1.9218x; 1.1922x over previous
#include <cuda_runtime.h>
#include <math.h>
#include <stdint.h>
#include <mma.h>
using namespace nvcuda;

#define BATCH_  32
#define DIM_    128
#define TLEN_   4096
#define HOP_    256
#define NFR_    17
#define NB_     257
#define SLEN_   4369
#define NPATCH_ 196
#define NFREQ_  99
#define OLA_    4608

static __device__ float  g_ecg_bdt[BATCH_*DIM_*TLEN_];
static __device__ float  g_xsum_bdt[BATCH_*DIM_*TLEN_];
static __device__ float2 g_fbeff  [DIM_*SLEN_];
static __device__ float2 g_Zimg   [BATCH_*NFREQ_*DIM_];
static __device__ float  g_gate   [BATCH_*DIM_];
static __device__ float  g_ximg   [BATCH_*NPATCH_*DIM_];
static __device__ float  g_normv  [OLA_];

// ======================= radix-8 FFT =======================
template<int SIGN>
__device__ __forceinline__ void fft8(float* r, float* i){
    const float c = 0.70710678118654752f;
    float ur[4], ui[4], vr[4], vi[4];
    #pragma unroll
    for (int q = 0; q < 4; q++){
        ur[q] = r[q] + r[q+4]; ui[q] = i[q] + i[q+4];
        vr[q] = r[q] - r[q+4]; vi[q] = i[q] - i[q+4];
    }
    { float x = vr[1], y = vi[1];
      if (SIGN < 0){ vr[1] = c*(x+y); vi[1] = c*(y-x); }
      else         { vr[1] = c*(x-y); vi[1] = c*(x+y); } }
    { float x = vr[2], y = vi[2];
      if (SIGN < 0){ vr[2] = y;  vi[2] = -x; }
      else         { vr[2] = -y; vi[2] = x;  } }
    { float x = vr[3], y = vi[3];
      if (SIGN < 0){ vr[3] = c*(y-x);  vi[3] = -c*(x+y); }
      else         { vr[3] = -c*(x+y); vi[3] = c*(x-y);  } }
    float p0r = ur[0]+ur[2], p0i = ui[0]+ui[2];
    float p2r = ur[0]-ur[2], p2i = ui[0]-ui[2];
    float p1r = ur[1]+ur[3], p1i = ui[1]+ui[3];
    float t3r = ur[1]-ur[3], t3i = ui[1]-ui[3];
    float p3r, p3i;
    if (SIGN < 0){ p3r = t3i; p3i = -t3r; } else { p3r = -t3i; p3i = t3r; }
    float q0r = vr[0]+vr[2], q0i = vi[0]+vi[2];
    float q2r = vr[0]-vr[2], q2i = vi[0]-vi[2];
    float q1r = vr[1]+vr[3], q1i = vi[1]+vi[3];
    float s3r = vr[1]-vr[3], s3i = vi[1]-vi[3];
    float q3r, q3i;
    if (SIGN < 0){ q3r = s3i; q3i = -s3r; } else { q3r = -s3i; q3i = s3r; }
    r[0] = p0r+p1r; i[0] = p0i+p1i;
    r[1] = p0r-p1r; i[1] = p0i-p1i;
    r[2] = p2r+p3r; i[2] = p2i+p3i;
    r[3] = p2r-p3r; i[3] = p2i-p3i;
    r[4] = q0r+q1r; i[4] = q0i+q1i;
    r[5] = q0r-q1r; i[5] = q0i-q1i;
    r[6] = q2r+q3r; i[6] = q2i+q3i;
    r[7] = q2r-q3r; i[7] = q2i-q3i;
}

#define PHYS(idx) ((idx) + ((idx) >> 3))

template<int SIGN, int S>
__device__ __forceinline__ void r8stage(const float* __restrict__ sR,
                                        const float* __restrict__ sI,
                                        float* __restrict__ dR,
                                        float* __restrict__ dI,
                                        const float* __restrict__ twR,
                                        const float* __restrict__ twI, int t){
    float xr[8], xi[8];
    #pragma unroll
    for (int q = 0; q < 8; q++){
        int idx = t + 64*q;
        xr[q] = sR[PHYS(idx)]; xi[q] = sI[PHYS(idx)];
    }
    fft8<SIGN>(xr, xi);
    const int brev[8] = {0,4,2,6,1,5,3,7};
    int hi = t / S, lo = t % S;
    int base = hi*8*S + lo;
    int tb = hi*S;
    #pragma unroll
    for (int j = 0; j < 8; j++){
        float yr = xr[brev[j]], yi = xi[brev[j]];
        int m = (tb*j) & 511;
        float wr = twR[m];
        float wi = (SIGN < 0) ? twI[m] : -twI[m];
        int idx = base + j*S;
        dR[PHYS(idx)] = yr*wr - yi*wi;
        dI[PHYS(idx)] = yr*wi + yi*wr;
    }
}

// group barrier: 64 threads (2 warps), ids 1..6
__device__ __forceinline__ void gbar(int id){
    asm volatile("bar.sync %0, %1;" :: "r"(id), "r"(64) : "memory");
}

// ======================= small kernels =========================================
__global__ void k_transpose(const float* __restrict__ in, float* __restrict__ out,
                            int R, int C){
    __shared__ float tile[32][33];
    size_t base = (size_t)blockIdx.z * R * C;
    int c0 = blockIdx.x*32, r0 = blockIdx.y*32;
    int tx = threadIdx.x, ty = threadIdx.y;
    #pragma unroll
    for (int k = 0; k < 32; k += 8)
        tile[ty+k][tx] = in[base + (size_t)(r0+ty+k)*C + c0+tx];
    __syncthreads();
    #pragma unroll
    for (int k = 0; k < 32; k += 8)
        out[base + (size_t)(c0+ty+k)*R + r0+tx] = tile[tx][ty+k];
}

__global__ void k_fbeff(const float2* __restrict__ tfb, float2* __restrict__ fbeff,
                        float c0, float c1){
    int s = blockIdx.x, d = threadIdx.x;
    int k = s / NFR_, fr = s % NFR_;
    float2 a = tfb[(size_t)s*DIM_ + d];
    float2 b = tfb[((size_t)SLEN_+s)*DIM_ + d];
    fbeff[(size_t)d*SLEN_ + fr*NB_ + k] =
        make_float2(c0*a.x + c1*b.x, c0*a.y + c1*b.y);
}

__global__ void k_norm(float* __restrict__ normv){
    int j = blockIdx.x*blockDim.x + threadIdx.x;
    if (j >= OLA_) return;
    float acc = 0.f;
    for (int fr = 0; fr < NFR_; fr++){
        int n = j - fr*HOP_;
        if (n >= 0 && n < 512){
            float w = 0.5f - 0.5f*cosf(6.283185307179586f*(float)n/512.f);
            acc += w*w;
        }
    }
    normv[j] = (acc > 1e-10f) ? acc : 1.f;
}

// ======================= fused STFT/filter/ISTFT ===============================
// 384 threads = 6 groups x 64; 2 (b,d) rows per block; 18 paired tasks, 3 each.
#define FS_SMEM 98304
__global__ void __launch_bounds__(384)
k_fsru(const float* __restrict__ ecg_bdt, const float2* __restrict__ fbeff,
       const float* __restrict__ normv, const float* __restrict__ gate,
       float* __restrict__ xsum){
    extern __shared__ float sm[];
    float* twR  = sm;
    float* twI  = sm + 512;
    float* win  = sm + 1024;
    float* ola0 = sm + 1536;
    float* ola1 = sm + 1536 + OLA_;
    float* bufs = sm + 1536 + 2*OLA_;
    int tid = threadIdx.x, g = tid / 64, t = tid % 64;
    int blk = blockIdx.x;
    int bd0 = 2*blk, bd1 = 2*blk + 1;
    float* AR = bufs + (g*4+0)*576;
    float* AI = bufs + (g*4+1)*576;
    float* BR = bufs + (g*4+2)*576;
    float* BI = bufs + (g*4+3)*576;
    for (int m = tid; m < 512; m += 384){
        float s, c;
        sincosf(6.283185307179586f*(float)m/512.f, &s, &c);
        twR[m] = c; twI[m] = -s;
        win[m] = 0.5f - 0.5f*c;
    }
    for (int j = tid; j < 2*OLA_; j += 384) ola0[j] = 0.f;
    const float*  x0 = ecg_bdt + (size_t)bd0*TLEN_;
    const float*  x1 = ecg_bdt + (size_t)bd1*TLEN_;
    const float2* fe0 = fbeff + (size_t)(bd0 & (DIM_-1))*SLEN_;
    const float2* fe1 = fbeff + (size_t)(bd1 & (DIM_-1))*SLEN_;
    const float sc = 1.f/(256.f*256.f*4369.f);
    const int bid = g + 1;
    __syncthreads();

    #pragma unroll
    for (int ti = 0; ti < 3; ti++){
        int task = 3*g + ti;                 // 0..17
        int row = task / 9, which = task % 9;
        const float*  x  = row ? x1 : x0;
        const float2* fe = row ? fe1 : fe0;
        float* ola = row ? ola1 : ola0;
        int fr_a, fr_b; bool hasb;
        if (which < 8){ fr_a = 2*which; fr_b = fr_a + 1; hasb = true; }
        else          { fr_a = 16; fr_b = 0; hasb = false; }
        // load two windowed frames packed as a + i b
        #pragma unroll
        for (int q = 0; q < 8; q++){
            int idx = t + 64*q;
            int ta = fr_a*HOP_ + idx - HOP_;
            float va = (ta >= 0 && ta < TLEN_) ? x[ta] : 0.f;
            float vb = 0.f;
            if (hasb){
                int tb2 = fr_b*HOP_ + idx - HOP_;
                vb = (tb2 >= 0 && tb2 < TLEN_) ? x[tb2] : 0.f;
            }
            AR[PHYS(idx)] = va*win[idx]; AI[PHYS(idx)] = vb*win[idx];
        }
        gbar(bid);
        r8stage<-1,1 >(AR,AI,BR,BI,twR,twI,t);
        gbar(bid);
        r8stage<-1,8 >(BR,BI,AR,AI,twR,twI,t);
        gbar(bid);
        r8stage<-1,64>(AR,AI,BR,BI,twR,twI,t);
        gbar(bid);
        // split A/B spectra, filter both, merge C = Ya + i*Yb into AR/AI
        #pragma unroll
        for (int q = 0; q < 8; q++){
            int k = t + 64*q;
            int km = (512 - k) & 511;
            float Zkr = BR[PHYS(k)],  Zki = BI[PHYS(k)];
            float Zmr = BR[PHYS(km)], Zmi = BI[PHYS(km)];
            float Ar  = 0.5f*(Zkr + Zmr), Aii = 0.5f*(Zki - Zmi);
            float Brr = 0.5f*(Zki + Zmi), Bii = 0.5f*(Zmr - Zkr);
            int m = (k <= 256) ? k : 512 - k;
            float sgn = (k <= 256) ? 1.f : -1.f;
            float2 fa = fe[fr_a*NB_ + m];
            float fai = sgn*fa.y;
            float a2r = (Ar*Ar - Aii*Aii)*sc, a2i = 2.f*Ar*Aii*sc;
            float Yar = a2r*fa.x - a2i*fai;
            float Yai = a2r*fai + a2i*fa.x;
            if (k == 0 || k == 256) Yai = 0.f;
            float Ybr = 0.f, Ybi = 0.f;
            if (hasb){
                float2 fb = fe[fr_b*NB_ + m];
                float fbi = sgn*fb.y;
                float b2r = (Brr*Brr - Bii*Bii)*sc, b2i = 2.f*Brr*Bii*sc;
                Ybr = b2r*fb.x - b2i*fbi;
                Ybi = b2r*fbi + b2i*fb.x;
                if (k == 0 || k == 256) Ybi = 0.f;
            }
            AR[PHYS(k)] = Yar - Ybi;
            AI[PHYS(k)] = Yai + Ybr;
        }
        gbar(bid);
        r8stage<1,1 >(AR,AI,BR,BI,twR,twI,t);
        gbar(bid);
        r8stage<1,8 >(BR,BI,AR,AI,twR,twI,t);
        gbar(bid);
        r8stage<1,64>(AR,AI,BR,BI,twR,twI,t);
        // final stage wrote exactly the positions this thread reads below
        #pragma unroll
        for (int q = 0; q < 8; q++){
            int n = t + 64*q;
            float wn = 0.5f*win[n];
            atomicAdd(&ola[fr_a*HOP_ + n], BR[PHYS(n)]*wn);
            if (hasb) atomicAdd(&ola[fr_b*HOP_ + n], BI[PHYS(n)]*wn);
        }
    }
    __syncthreads();
    float gv0 = gate[bd0], gv1 = gate[bd1];
    float* xo0 = xsum + (size_t)bd0*TLEN_;
    float* xo1 = xsum + (size_t)bd1*TLEN_;
    for (int tau = tid; tau < TLEN_; tau += 384){
        int j = tau + HOP_;
        float nv = normv[j];
        xo0[tau] = (ola0[j]/nv)*gv0 + x0[tau];
        xo1[tau] = (ola1[j]/nv)*gv1 + x1[tau];
    }
}

// ======================= image path ============================================
__global__ void k_imgfft(const float* __restrict__ image, const float2* __restrict__ ifb,
                         float2* __restrict__ Zimg, float c0, float c1){
    int f = blockIdx.x, b = blockIdx.y, d = threadIdx.x;
    __shared__ float cs[NPATCH_], sn[NPATCH_];
    for (int n = d; n < NPATCH_; n += DIM_){
        int m = (f*n) % NPATCH_;
        float s, c;
        sincosf(-6.283185307179586f*(float)m/(float)NPATCH_, &s, &c);
        cs[n] = c; sn[n] = s;
    }
    __syncthreads();
    const float* xb = image + (size_t)b*NPATCH_*DIM_;
    float ar = 0.f, ai = 0.f;
    for (int n = 0; n < NPATCH_; n++){
        float v = xb[n*DIM_ + d];
        ar = fmaf(v, cs[n], ar);
        ai = fmaf(v, sn[n], ai);
    }
    ar *= (1.f/14.f); ai *= (1.f/14.f);
    float2 fa = ifb[((size_t)0*NFREQ_+f)*DIM_ + d];
    float2 fb = ifb[((size_t)1*NFREQ_+f)*DIM_ + d];
    float2 feff = make_float2(c0*fa.x+c1*fb.x, c0*fa.y+c1*fb.y);
    float z2r = (ar*ar - ai*ai)*(1.f/99.f), z2i = 2.f*ar*ai*(1.f/99.f);
    Zimg[((size_t)b*NFREQ_+f)*DIM_ + d] =
        make_float2(z2r*feff.x - z2i*feff.y, z2r*feff.y + z2i*feff.x);
}

__global__ void k_gate(const float2* __restrict__ Zimg, const float2* __restrict__ sel,
                       const float* __restrict__ w, const float* __restrict__ bias,
                       float* __restrict__ gate){
    int b = blockIdx.x, d = threadIdx.x;
    __shared__ float g[DIM_];
    float acc = 0.f;
    for (int f = 0; f < NFREQ_; f++){
        float2 z = Zimg[((size_t)b*NFREQ_+f)*DIM_ + d];
        float2 s = sel[(size_t)f*DIM_ + d];
        acc += z.x*s.x - z.y*s.y;
    }
    g[d] = acc*(1.f/99.f);
    __syncthreads();
    float o = bias[d];
    for (int k = 0; k < DIM_; k++) o = fmaf(g[k], w[d*DIM_+k], o);
    gate[b*DIM_+d] = o;
}

__global__ void k_imgirfft(const float2* __restrict__ Zimg, const float* __restrict__ image,
                           float* __restrict__ ximg){
    int n = blockIdx.x, b = blockIdx.y, d = threadIdx.x;
    __shared__ float cs[NFREQ_], sn[NFREQ_];
    for (int f = d; f < NFREQ_; f += DIM_){
        int m = (f*n) % NPATCH_;
        float s, c;
        sincosf(6.283185307179586f*(float)m/(float)NPATCH_, &s, &c);
        cs[f] = c; sn[f] = s;
    }
    __syncthreads();
    const float2* Zb = Zimg + (size_t)b*NFREQ_*DIM_;
    float acc = 0.f;
    #pragma unroll 4
    for (int f = 0; f < NFREQ_; f++){
        float wgt = (f == 0 || f == NFREQ_-1) ? 1.f : 2.f;
        float2 z = Zb[f*DIM_ + d];
        acc += wgt*(z.x*cs[f] - z.y*sn[f]);
    }
    size_t idx = ((size_t)b*NPATCH_ + n)*DIM_ + d;
    ximg[idx] = acc*(1.f/14.f) + image[idx];
}

// ======================= wmma tf32 AddNorm (64 rows, streamed weights) =========
#define LDM_ 136
#define AW_SMEM (2*64*LDM_*4)

__global__ void __launch_bounds__(256)
k_addnorm_w(const float* __restrict__ xin, float* __restrict__ out, int trans,
            const float* __restrict__ g1, const float* __restrict__ b1,
            const float* __restrict__ w1, const float* __restrict__ bb1,
            const float* __restrict__ w2, const float* __restrict__ bb2,
            const float* __restrict__ g2, const float* __restrict__ b2){
    extern __shared__ float sm[];
    float* X = sm;                // post-LN1 x (A of GEMM1 + residual)
    float* H = sm + 64*LDM_;      // C1 -> gelu -> A of GEMM2 -> C2
    const int tid = threadIdx.x, warp = tid>>5, lane = tid&31;
    const int wm = warp >> 2, wn = warp & 3;   // rows wm*32, cols wn*32

    size_t row0 = (size_t)blockIdx.x * 64;
    if (trans){
        int b = (int)(row0 >> 12), tok0 = (int)(row0 & 4095);
        const float* xb = xin + ((size_t)b*DIM_)*TLEN_ + tok0;
        for (int i = tid; i < 64*128; i += 256){
            int dd = i >> 6, tok = i & 63;
            X[tok*LDM_ + dd] = xb[(size_t)dd*TLEN_ + tok];
        }
    } else {
        const float* xb = xin + row0*DIM_;
        for (int i = tid; i < 64*128; i += 256)
            X[(i>>7)*LDM_ + (i&127)] = xb[i];
    }
    __syncthreads();

    // LN1: 8 warps x 8 rows, in place
    float gv[4], bv[4];
    #pragma unroll
    for (int j = 0; j < 4; j++){ gv[j] = g1[lane+32*j]; bv[j] = b1[lane+32*j]; }
    for (int rr = 0; rr < 8; rr++){
        int r = warp*8 + rr;
        float v[4];
        #pragma unroll
        for (int j = 0; j < 4; j++) v[j] = X[r*LDM_ + lane+32*j];
        float s = v[0]+v[1]+v[2]+v[3];
        #pragma unroll
        for (int o = 16; o; o >>= 1) s += __shfl_xor_sync(0xffffffffu, s, o);
        float mn = s*(1.f/128.f), q = 0.f;
        #pragma unroll
        for (int j = 0; j < 4; j++){ v[j] -= mn; q += v[j]*v[j]; }
        #pragma unroll
        for (int o = 16; o; o >>= 1) q += __shfl_xor_sync(0xffffffffu, q, o);
        float inv = rsqrtf(q*(1.f/128.f) + 1e-5f);
        #pragma unroll
        for (int j = 0; j < 4; j++)
            X[r*LDM_ + lane+32*j] = v[j]*inv*gv[j] + bv[j];
    }
    __syncthreads();

    // GEMM1: H = X @ w1  (B streamed from global / L2)
    wmma::fragment<wmma::accumulator, 16, 16, 8, float> acc[2][2];
    #pragma unroll
    for (int i = 0; i < 2; i++)
        #pragma unroll
        for (int j = 0; j < 2; j++) wmma::fill_fragment(acc[i][j], 0.f);
    #pragma unroll 4
    for (int kk = 0; kk < 128; kk += 8){
        wmma::fragment<wmma::matrix_a, 16, 16, 8, wmma::precision::tf32, wmma::row_major> af[2];
        wmma::fragment<wmma::matrix_b, 16, 16, 8, wmma::precision::tf32, wmma::row_major> bf[2];
        #pragma unroll
        for (int i = 0; i < 2; i++){
            wmma::load_matrix_sync(af[i], X + (wm*32 + i*16)*LDM_ + kk, LDM_);
            #pragma unroll
            for (int e = 0; e < af[i].num_elements; e++)
                af[i].x[e] = wmma::__float_to_tf32(af[i].x[e]);
        }
        #pragma unroll
        for (int j = 0; j < 2; j++){
            wmma::load_matrix_sync(bf[j], w1 + kk*128 + wn*32 + j*16, 128);
            #pragma unroll
            for (int e = 0; e < bf[j].num_elements; e++)
                bf[j].x[e] = wmma::__float_to_tf32(bf[j].x[e]);
        }
        #pragma unroll
        for (int i = 0; i < 2; i++)
            #pragma unroll
            for (int j = 0; j < 2; j++)
                wmma::mma_sync(acc[i][j], af[i], bf[j], acc[i][j]);
    }
    #pragma unroll
    for (int i = 0; i < 2; i++)
        #pragma unroll
        for (int j = 0; j < 2; j++)
            wmma::store_matrix_sync(H + (wm*32 + i*16)*LDM_ + wn*32 + j*16,
                                    acc[i][j], LDM_, wmma::mem_row_major);
    __syncthreads();

    // gelu(H + bb1) in place
    for (int i = tid; i < 64*128; i += 256){
        int r = i >> 7, c = i & 127;
        float h = H[r*LDM_ + c] + bb1[c];
        H[r*LDM_ + c] = 0.5f*h*(1.f + erff(h*0.70710678118654752f));
    }
    __syncthreads();

    // GEMM2: C2 = gelu(H) @ w2  (B streamed from global / L2)
    #pragma unroll
    for (int i = 0; i < 2; i++)
        #pragma unroll
        for (int j = 0; j < 2; j++) wmma::fill_fragment(acc[i][j], 0.f);
    #pragma unroll 4
    for (int kk = 0; kk < 128; kk += 8){
        wmma::fragment<wmma::matrix_a, 16, 16, 8, wmma::precision::tf32, wmma::row_major> af[2];
        wmma::fragment<wmma::matrix_b, 16, 16, 8, wmma::precision::tf32, wmma::row_major> bf[2];
        #pragma unroll
        for (int i = 0; i < 2; i++){
            wmma::load_matrix_sync(af[i], H + (wm*32 + i*16)*LDM_ + kk, LDM_);
            #pragma unroll
            for (int e = 0; e < af[i].num_elements; e++)
                af[i].x[e] = wmma::__float_to_tf32(af[i].x[e]);
        }
        #pragma unroll
        for (int j = 0; j < 2; j++){
            wmma::load_matrix_sync(bf[j], w2 + kk*128 + wn*32 + j*16, 128);
            #pragma unroll
            for (int e = 0; e < bf[j].num_elements; e++)
                bf[j].x[e] = wmma::__float_to_tf32(bf[j].x[e]);
        }
        #pragma unroll
        for (int i = 0; i < 2; i++)
            #pragma unroll
            for (int j = 0; j < 2; j++)
                wmma::mma_sync(acc[i][j], af[i], bf[j], acc[i][j]);
    }
    __syncthreads();    // all reads of H complete before overwrite
    #pragma unroll
    for (int i = 0; i < 2; i++)
        #pragma unroll
        for (int j = 0; j < 2; j++)
            wmma::store_matrix_sync(H + (wm*32 + i*16)*LDM_ + wn*32 + j*16,
                                    acc[i][j], LDM_, wmma::mem_row_major);
    __syncthreads();

    // residual + LN2 -> out
    #pragma unroll
    for (int j = 0; j < 4; j++){ gv[j] = g2[lane+32*j]; bv[j] = b2[lane+32*j]; }
    for (int rr = 0; rr < 8; rr++){
        int r = warp*8 + rr;
        float v[4];
        #pragma unroll
        for (int j = 0; j < 4; j++){
            int c = lane + 32*j;
            v[j] = H[r*LDM_ + c] + bb2[c] + X[r*LDM_ + c];
        }
        float s = v[0]+v[1]+v[2]+v[3];
        #pragma unroll
        for (int o = 16; o; o >>= 1) s += __shfl_xor_sync(0xffffffffu, s, o);
        float mn = s*(1.f/128.f), q = 0.f;
        #pragma unroll
        for (int j = 0; j < 4; j++){ v[j] -= mn; q += v[j]*v[j]; }
        #pragma unroll
        for (int o = 16; o; o >>= 1) q += __shfl_xor_sync(0xffffffffu, q, o);
        float inv = rsqrtf(q*(1.f/128.f) + 1e-5f);
        #pragma unroll
        for (int j = 0; j < 4; j++)
            out[(row0 + r)*DIM_ + lane+32*j] = v[j]*inv*gv[j] + bv[j];
    }
}

// ======================= launch ================================================
extern "C" void kernel_launch(void* const* d_in, const int* in_sizes, int n_in,
                              void* d_out, int out_size){
    (void)in_sizes; (void)n_in; (void)out_size;
    const float* ecg     = (const float*)d_in[0];
    const float* image   = (const float*)d_in[1];
    const float* tfb     = (const float*)d_in[2];
    const float* ifb     = (const float*)d_in[3];
    const float* i2t_sel = (const float*)d_in[4];
    const float* i2t_w   = (const float*)d_in[5];
    const float* i2t_b   = (const float*)d_in[6];
    const float* t_ln1_g = (const float*)d_in[7];
    const float* t_ln1_b = (const float*)d_in[8];
    const float* t_w1    = (const float*)d_in[9];
    const float* t_b1    = (const float*)d_in[10];
    const float* t_w2    = (const float*)d_in[11];
    const float* t_b2    = (const float*)d_in[12];
    const float* t_ln2_g = (const float*)d_in[13];
    const float* t_ln2_b = (const float*)d_in[14];
    const float* i_ln1_g = (const float*)d_in[15];
    const float* i_ln1_b = (const float*)d_in[16];
    const float* i_w1    = (const float*)d_in[17];
    const float* i_b1    = (const float*)d_in[18];
    const float* i_w2    = (const float*)d_in[19];
    const float* i_b2    = (const float*)d_in[20];
    const float* i_ln2_g = (const float*)d_in[21];
    const float* i_ln2_b = (const float*)d_in[22];

    void* p;
    cudaGetSymbolAddress(&p, g_ecg_bdt);  float*  ecg_bdt = (float*)p;
    cudaGetSymbolAddress(&p, g_xsum_bdt); float*  xsum    = (float*)p;
    cudaGetSymbolAddress(&p, g_fbeff);    float2* fbeff   = (float2*)p;
    cudaGetSymbolAddress(&p, g_Zimg);     float2* Zimg    = (float2*)p;
    cudaGetSymbolAddress(&p, g_gate);     float*  gate    = (float*)p;
    cudaGetSymbolAddress(&p, g_ximg);     float*  ximg    = (float*)p;
    cudaGetSymbolAddress(&p, g_normv);    float*  normv   = (float*)p;

    float c0 = cosf(1.f*3.1415926f);
    float c1 = cosf(3.f*3.1415926f);

    cudaFuncSetAttribute(k_fsru, cudaFuncAttributeMaxDynamicSharedMemorySize, FS_SMEM);
    cudaFuncSetAttribute(k_addnorm_w, cudaFuncAttributeMaxDynamicSharedMemorySize, AW_SMEM);

    float* text_out = (float*)d_out;
    float* img_out  = (float*)d_out + (size_t)BATCH_*TLEN_*DIM_;

    k_transpose<<<dim3(DIM_/32, TLEN_/32, BATCH_), dim3(32,8)>>>(ecg, ecg_bdt, TLEN_, DIM_);
    k_fbeff<<<SLEN_, DIM_>>>((const float2*)tfb, fbeff, c0, c1);
    k_norm<<<(OLA_+255)/256, 256>>>(normv);
    k_imgfft<<<dim3(NFREQ_, BATCH_), DIM_>>>(image, (const float2*)ifb, Zimg, c0, c1);
    k_gate<<<BATCH_, DIM_>>>(Zimg, (const float2*)i2t_sel, i2t_w, i2t_b, gate);
    k_fsru<<<BATCH_*DIM_/2, 384, FS_SMEM>>>(ecg_bdt, fbeff, normv, gate, xsum);
    k_addnorm_w<<<(BATCH_*TLEN_)/64, 256, AW_SMEM>>>(xsum, text_out, 1,
        t_ln1_g, t_ln1_b, t_w1, t_b1, t_w2, t_b2, t_ln2_g, t_ln2_b);
    k_imgirfft<<<dim3(NPATCH_, BATCH_), DIM_>>>(Zimg, image, ximg);
    k_addnorm_w<<<(BATCH_*NPATCH_)/64, 256, AW_SMEM>>>(ximg, img_out, 0,
        i_ln1_g, i_ln1_b, i_w1, i_b1, i_w2, i_b2, i_ln2_g, i_ln2_b);
}